// round 2
// baseline (speedup 1.0000x reference)
#include <cuda_runtime.h>
#include <math.h>

#define DIMN   1024
#define NHEADS 16
#define HDIM   64
#define LORA_D 16
#define BB     4
#define TT     1024
#define MTOK   (BB*TT)   // 4096

// ---------------- scratch (static device allocations; no cudaMalloc) ----------------
__device__ float g_h[MTOK*48];
__device__ float g_qin[MTOK*DIMN];
__device__ float g_kin[MTOK*DIMN];
__device__ float g_vin[MTOK*DIMN];
__device__ float g_q[MTOK*DIMN];
__device__ float g_k[MTOK*DIMN];
__device__ float g_v[MTOK*DIMN];
__device__ float g_attn[MTOK*DIMN];

// ---------------- kernel 1: H = tanh(x @ Acat^T), Acat = [q_a; k_a; v_a] (48 x 1024) ----------
__global__ void __launch_bounds__(256) lora_h_kernel(const float* __restrict__ x,
                                                     const float* __restrict__ qa,
                                                     const float* __restrict__ ka,
                                                     const float* __restrict__ va) {
    __shared__ float xs[8][DIMN];          // 32KB
    const int tok0 = blockIdx.x * 8;
    const int tid  = threadIdx.x;

    const float4* xg  = (const float4*)(x + (size_t)tok0 * DIMN);
    float4*       xs4 = (float4*)&xs[0][0];
#pragma unroll
    for (int i = 0; i < 8; i++) xs4[tid + i*256] = xg[tid + i*256];
    __syncthreads();

    const int warp = tid >> 5, lane = tid & 31;
#pragma unroll
    for (int jj = 0; jj < 6; jj++) {
        const int j = warp * 6 + jj;       // 0..47
        const float* a = (j < 16) ? (qa + j*DIMN)
                       : (j < 32) ? (ka + (j-16)*DIMN)
                                  : (va + (j-32)*DIMN);
        float acc[8];
#pragma unroll
        for (int t = 0; t < 8; t++) acc[t] = 0.f;
        for (int i = 0; i < 32; i++) {
            float av = a[lane + i*32];
#pragma unroll
            for (int t = 0; t < 8; t++) acc[t] += xs[t][lane + i*32] * av;
        }
#pragma unroll
        for (int off = 16; off; off >>= 1) {
#pragma unroll
            for (int t = 0; t < 8; t++)
                acc[t] += __shfl_xor_sync(0xffffffffu, acc[t], off);
        }
        if (lane == 0) {
#pragma unroll
            for (int t = 0; t < 8; t++)
                g_h[(size_t)(tok0 + t)*48 + j] = tanhf(acc[t]);
        }
    }
}

// ---------------- kernel 2: qin/kin/vin = x + (xprev - x) * (lam + H @ b^T) ----------------
__global__ void __launch_bounds__(256) mod_input_kernel(const float* __restrict__ x,
                                                        const float* __restrict__ qb, const float* __restrict__ ql,
                                                        const float* __restrict__ kb, const float* __restrict__ kl,
                                                        const float* __restrict__ vb, const float* __restrict__ vl) {
    const int which = blockIdx.y;                 // 0=q 1=k 2=v
    const int tok0  = blockIdx.x * 32;
    const float* b = (which == 0) ? qb : (which == 1) ? kb : vb;
    const float* l = (which == 0) ? ql : (which == 1) ? kl : vl;
    float* out = (which == 0) ? g_qin : (which == 1) ? g_kin : g_vin;

    __shared__ float hs[32][LORA_D];
    const int tid = threadIdx.x;
    for (int i = tid; i < 32*LORA_D; i += 256) {
        int t = i >> 4, j = i & 15;
        hs[t][j] = g_h[(size_t)(tok0 + t)*48 + which*16 + j];
    }
    __syncthreads();

#pragma unroll
    for (int c = 0; c < 4; c++) {
        const int d = tid + c*256;
        float bv[LORA_D];
        const float4* brow = (const float4*)(b + (size_t)d * LORA_D);
#pragma unroll
        for (int q4 = 0; q4 < 4; q4++) {
            float4 w = brow[q4];
            bv[q4*4+0] = w.x; bv[q4*4+1] = w.y; bv[q4*4+2] = w.z; bv[q4*4+3] = w.w;
        }
        const float lam = l[d];
        float xprev = ((tok0 % TT) == 0) ? 0.f : x[(size_t)(tok0 - 1)*DIMN + d];
        for (int t = 0; t < 32; t++) {
            float xv = x[(size_t)(tok0 + t)*DIMN + d];
            float lr = lam;
#pragma unroll
            for (int j = 0; j < LORA_D; j++) lr += hs[t][j] * bv[j];
            out[(size_t)(tok0 + t)*DIMN + d] = xv + (xprev - xv) * lr;
            xprev = xv;
        }
    }
}

// ---------------- kernel 3: C = A @ W^T (+bias).  A:4096x1024, W:1024x1024 ----------------
__global__ void __launch_bounds__(256, 2) sgemm_nt_kernel(const float* __restrict__ A,
                                                          const float* __restrict__ W,
                                                          const float* __restrict__ bias,
                                                          float* __restrict__ C) {
    __shared__ float As[8][132];
    __shared__ float Ws[8][132];
    const int tid = threadIdx.x;
    const int tx = tid & 15, ty = tid >> 4;
    const int m0 = blockIdx.y * 128, n0 = blockIdx.x * 128;

    float acc[8][8];
#pragma unroll
    for (int i = 0; i < 8; i++)
#pragma unroll
        for (int j = 0; j < 8; j++) acc[i][j] = 0.f;

    const float* Ag = A + (size_t)m0 * 1024;
    const float* Wg = W + (size_t)n0 * 1024;

    for (int k0 = 0; k0 < 1024; k0 += 8) {
#pragma unroll
        for (int e = 0; e < 4; e++) {
            int idx = tid + e*256;
            int row = idx >> 3, kk = idx & 7;
            As[kk][row] = Ag[(size_t)row*1024 + k0 + kk];
            Ws[kk][row] = Wg[(size_t)row*1024 + k0 + kk];
        }
        __syncthreads();
#pragma unroll
        for (int kk = 0; kk < 8; kk++) {
            float4 a0 = *(const float4*)&As[kk][ty*8];
            float4 a1 = *(const float4*)&As[kk][ty*8 + 4];
            float4 b0 = *(const float4*)&Ws[kk][tx*8];
            float4 b1 = *(const float4*)&Ws[kk][tx*8 + 4];
            float aa[8] = {a0.x, a0.y, a0.z, a0.w, a1.x, a1.y, a1.z, a1.w};
            float bb[8] = {b0.x, b0.y, b0.z, b0.w, b1.x, b1.y, b1.z, b1.w};
#pragma unroll
            for (int i = 0; i < 8; i++)
#pragma unroll
                for (int j = 0; j < 8; j++) acc[i][j] += aa[i] * bb[j];
        }
        __syncthreads();
    }

#pragma unroll
    for (int i = 0; i < 8; i++) {
        const int m = m0 + ty*8 + i;
#pragma unroll
        for (int j = 0; j < 8; j++) {
            const int n = n0 + tx*8 + j;
            float vv = acc[i][j];
            if (bias) vv += bias[n];
            C[(size_t)m*1024 + n] = vv;
        }
    }
}

// ---------------- kernel 4: RoPE in-place on q and k ----------------
__global__ void __launch_bounds__(256) rope_kernel(float* __restrict__ q, float* __restrict__ k) {
    const int gid = blockIdx.x * 256 + threadIdx.x;       // 0 .. 2*2^21-1
    float* p = (gid >> 21) ? k : q;
    const int e = gid & ((1 << 21) - 1);
    const int j = e & 31;
    const int h = (e >> 5) & 15;
    const int t = (e >> 9) & 1023;
    const int b = e >> 19;
    const size_t base = ((size_t)(b*TT + t))*DIMN + h*HDIM;

    float theta = 1.0f / powf(10000.0f, (float)j * (1.0f / 32.0f));
    float ang = (float)t * theta;
    float sn, cs;
    sincosf(ang, &sn, &cs);
    float xr = p[base + j];
    float xi = p[base + j + 32];
    p[base + j]      = xr*cs - xi*sn;
    p[base + j + 32] = xr*sn + xi*cs;
}

// ---------------- kernel 5: causal flash attention (fp32), out in (B,T,H*D) layout ----------
#define ATT_SMEM_BYTES ((2*64*68 + 64*64 + 64*65)*4)   // 67840

__global__ void __launch_bounds__(256) attention_kernel(const float* __restrict__ q,
                                                        const float* __restrict__ k,
                                                        const float* __restrict__ v,
                                                        float* __restrict__ o) {
    extern __shared__ float sm[];
    float* Qts = sm;                          // [64 d][68]: Qts[d*68 + r]
    float* Kts = sm + 64*68;                  // [64 d][68]: Kts[d*68 + c]
    float* Vs  = sm + 2*64*68;                // [64 c][64]: Vs[c*64 + d]
    float* Ps  = sm + 2*64*68 + 64*64;        // [64 r][65]: Ps[r*65 + c]

    const int tid = threadIdx.x;
    const int tx = tid & 15, ty = tid >> 4;
    const int qt = blockIdx.x;                // 16 q-tiles
    const int bh = blockIdx.y;                // 64 (b,h)
    const int b = bh >> 4, h = bh & 15;
    const int q0 = qt * 64;

    const float* qg = q + ((size_t)b*TT)*DIMN + h*HDIM;
    const float* kg = k + ((size_t)b*TT)*DIMN + h*HDIM;
    const float* vg = v + ((size_t)b*TT)*DIMN + h*HDIM;

#pragma unroll
    for (int e = 0; e < 16; e++) {
        int idx = tid + e*256;
        int r = idx >> 6, d = idx & 63;
        Qts[d*68 + r] = qg[(size_t)(q0 + r)*DIMN + d];
    }

    float m_i[4], l_i[4], oacc[4][4];
#pragma unroll
    for (int i = 0; i < 4; i++) {
        m_i[i] = -1e30f; l_i[i] = 0.f;
#pragma unroll
        for (int j = 0; j < 4; j++) oacc[i][j] = 0.f;
    }

    for (int kt = 0; kt <= qt; kt++) {
        const int k0 = kt * 64;
        __syncthreads();                      // covers Q store (1st iter) + Vs/Kts reuse
#pragma unroll
        for (int e = 0; e < 16; e++) {
            int idx = tid + e*256;
            int r = idx >> 6, d = idx & 63;
            size_t gofs = (size_t)(k0 + r)*DIMN + d;
            Kts[d*68 + r] = kg[gofs];
            Vs[r*64 + d]  = vg[gofs];
        }
        __syncthreads();

        float s[4][4];
#pragma unroll
        for (int i = 0; i < 4; i++)
#pragma unroll
            for (int j = 0; j < 4; j++) s[i][j] = 0.f;

        for (int dd = 0; dd < 64; dd++) {
            float4 av = *(const float4*)&Qts[dd*68 + ty*4];
            float4 bv = *(const float4*)&Kts[dd*68 + tx*4];
            float aa[4] = {av.x, av.y, av.z, av.w};
            float bb[4] = {bv.x, bv.y, bv.z, bv.w};
#pragma unroll
            for (int i = 0; i < 4; i++)
#pragma unroll
                for (int j = 0; j < 4; j++) s[i][j] += aa[i] * bb[j];
        }

#pragma unroll
        for (int i = 0; i < 4; i++)
#pragma unroll
            for (int j = 0; j < 4; j++) s[i][j] *= 0.125f;

        if (kt == qt) {
#pragma unroll
            for (int i = 0; i < 4; i++)
#pragma unroll
                for (int j = 0; j < 4; j++)
                    if (tx*4 + j > ty*4 + i) s[i][j] = -1e30f;
        }

#pragma unroll
        for (int i = 0; i < 4; i++) {
            float mt = fmaxf(fmaxf(s[i][0], s[i][1]), fmaxf(s[i][2], s[i][3]));
#pragma unroll
            for (int off = 8; off; off >>= 1)
                mt = fmaxf(mt, __shfl_xor_sync(0xffffffffu, mt, off));
            float m_new = fmaxf(m_i[i], mt);
            float corr = __expf(m_i[i] - m_new);
            float rs = 0.f;
#pragma unroll
            for (int j = 0; j < 4; j++) {
                float pp = __expf(s[i][j] - m_new);
                s[i][j] = pp;
                rs += pp;
            }
#pragma unroll
            for (int off = 8; off; off >>= 1)
                rs += __shfl_xor_sync(0xffffffffu, rs, off);
            l_i[i] = l_i[i] * corr + rs;
            m_i[i] = m_new;
#pragma unroll
            for (int j = 0; j < 4; j++) oacc[i][j] *= corr;
        }

#pragma unroll
        for (int i = 0; i < 4; i++)
#pragma unroll
            for (int j = 0; j < 4; j++)
                Ps[(ty*4 + i)*65 + tx*4 + j] = s[i][j];
        __syncthreads();

        for (int cc = 0; cc < 64; cc++) {
            float4 vv = *(const float4*)&Vs[cc*64 + tx*4];
            float vj[4] = {vv.x, vv.y, vv.z, vv.w};
#pragma unroll
            for (int i = 0; i < 4; i++) {
                float pp = Ps[(ty*4 + i)*65 + cc];
#pragma unroll
                for (int j = 0; j < 4; j++) oacc[i][j] += pp * vj[j];
            }
        }
    }

    float* og = o + ((size_t)b*TT + q0)*DIMN + h*HDIM;
#pragma unroll
    for (int i = 0; i < 4; i++) {
        float inv = 1.0f / l_i[i];
#pragma unroll
        for (int j = 0; j < 4; j++)
            og[(size_t)(ty*4 + i)*DIMN + tx*4 + j] = oacc[i][j] * inv;
    }
}

// ---------------- launch ----------------
extern "C" void kernel_launch(void* const* d_in, const int* in_sizes, int n_in,
                              void* d_out, int out_size) {
    const float* x      = (const float*)d_in[0];
    const float* q_w    = (const float*)d_in[1];
    const float* k_w    = (const float*)d_in[2];
    const float* v_w    = (const float*)d_in[3];
    const float* q_a    = (const float*)d_in[4];
    const float* q_b    = (const float*)d_in[5];
    const float* q_l    = (const float*)d_in[6];
    const float* k_a    = (const float*)d_in[7];
    const float* k_b    = (const float*)d_in[8];
    const float* k_l    = (const float*)d_in[9];
    const float* v_a    = (const float*)d_in[10];
    const float* v_b    = (const float*)d_in[11];
    const float* v_l    = (const float*)d_in[12];
    const float* proj_w = (const float*)d_in[13];
    const float* proj_b = (const float*)d_in[14];
    float* out = (float*)d_out;

    float *p_qin, *p_kin, *p_vin, *p_q, *p_k, *p_v, *p_attn;
    cudaGetSymbolAddress((void**)&p_qin,  g_qin);
    cudaGetSymbolAddress((void**)&p_kin,  g_kin);
    cudaGetSymbolAddress((void**)&p_vin,  g_vin);
    cudaGetSymbolAddress((void**)&p_q,    g_q);
    cudaGetSymbolAddress((void**)&p_k,    g_k);
    cudaGetSymbolAddress((void**)&p_v,    g_v);
    cudaGetSymbolAddress((void**)&p_attn, g_attn);

    cudaFuncSetAttribute(attention_kernel,
                         cudaFuncAttributeMaxDynamicSharedMemorySize, ATT_SMEM_BYTES);

    lora_h_kernel<<<MTOK/8, 256>>>(x, q_a, k_a, v_a);
    mod_input_kernel<<<dim3(MTOK/32, 3), 256>>>(x, q_b, q_l, k_b, k_l, v_b, v_l);
    sgemm_nt_kernel<<<dim3(8, 32), 256>>>(p_qin, q_w, nullptr, p_q);
    sgemm_nt_kernel<<<dim3(8, 32), 256>>>(p_kin, k_w, nullptr, p_k);
    sgemm_nt_kernel<<<dim3(8, 32), 256>>>(p_vin, v_w, nullptr, p_v);
    rope_kernel<<<(2*MTOK*NHEADS*32)/256, 256>>>(p_q, p_k);
    attention_kernel<<<dim3(16, 64), 256, ATT_SMEM_BYTES>>>(p_q, p_k, p_v, p_attn);
    sgemm_nt_kernel<<<dim3(8, 32), 256>>>(p_attn, proj_w, proj_b, out);
}

// round 4
// speedup vs baseline: 1.7985x; 1.7985x over previous
#include <cuda_runtime.h>
#include <cuda_bf16.h>
#include <cstdint>
#include <stdint.h>
#include <math.h>

#define DIMN   1024
#define NHEADS 16
#define HDIM   64
#define LORA_D 16
#define BB     4
#define TT     1024
#define MTOK   (BB*TT)   // 4096
#define KCAT   3072      // 3x split concat K

// ---------------- scratch (static device allocations; no cudaMalloc) ----------------
__device__ float g_h[MTOK*48];
__device__ __nv_bfloat16 g_qcat[(size_t)MTOK*KCAT];
__device__ __nv_bfloat16 g_kcat[(size_t)MTOK*KCAT];
__device__ __nv_bfloat16 g_vcat[(size_t)MTOK*KCAT];
__device__ __nv_bfloat16 g_wcat[(size_t)DIMN*KCAT];
__device__ float g_q[MTOK*DIMN];
__device__ float g_k[MTOK*DIMN];
__device__ float g_v[MTOK*DIMN];
__device__ float g_attn[MTOK*DIMN];

// ---------------- asm helpers ----------------
__device__ __forceinline__ void cpa16(unsigned int d, const void* s) {
    asm volatile("cp.async.cg.shared.global [%0], [%1], 16;\n" :: "r"(d), "l"(s));
}
__device__ __forceinline__ void ldsm4(unsigned int a, unsigned int* r) {
    asm volatile("ldmatrix.sync.aligned.m8n8.x4.shared.b16 {%0,%1,%2,%3}, [%4];\n"
        : "=r"(r[0]), "=r"(r[1]), "=r"(r[2]), "=r"(r[3]) : "r"(a));
}
__device__ __forceinline__ void mma16816(float* c, const unsigned int* a, unsigned int b0, unsigned int b1) {
    asm volatile("mma.sync.aligned.m16n8k16.row.col.f32.bf16.bf16.f32 "
        "{%0,%1,%2,%3},{%4,%5,%6,%7},{%8,%9},{%0,%1,%2,%3};\n"
        : "+f"(c[0]), "+f"(c[1]), "+f"(c[2]), "+f"(c[3])
        : "r"(a[0]), "r"(a[1]), "r"(a[2]), "r"(a[3]), "r"(b0), "r"(b1));
}

// ---------------- kernel 1: H = tanh(x @ Acat^T), Acat = [q_a; k_a; v_a] (48 x 1024) ----------
__global__ void __launch_bounds__(256) lora_h_kernel(const float* __restrict__ x,
                                                     const float* __restrict__ qa,
                                                     const float* __restrict__ ka,
                                                     const float* __restrict__ va) {
    __shared__ float xs[8][DIMN];
    const int tok0 = blockIdx.x * 8;
    const int tid  = threadIdx.x;

    const float4* xg  = (const float4*)(x + (size_t)tok0 * DIMN);
    float4*       xs4 = (float4*)&xs[0][0];
#pragma unroll
    for (int i = 0; i < 8; i++) xs4[tid + i*256] = xg[tid + i*256];
    __syncthreads();

    const int warp = tid >> 5, lane = tid & 31;
#pragma unroll
    for (int jj = 0; jj < 6; jj++) {
        const int j = warp * 6 + jj;
        const float* a = (j < 16) ? (qa + j*DIMN)
                       : (j < 32) ? (ka + (j-16)*DIMN)
                                  : (va + (j-32)*DIMN);
        float acc[8];
#pragma unroll
        for (int t = 0; t < 8; t++) acc[t] = 0.f;
        for (int i = 0; i < 32; i++) {
            float av = a[lane + i*32];
#pragma unroll
            for (int t = 0; t < 8; t++) acc[t] += xs[t][lane + i*32] * av;
        }
#pragma unroll
        for (int off = 16; off; off >>= 1) {
#pragma unroll
            for (int t = 0; t < 8; t++)
                acc[t] += __shfl_xor_sync(0xffffffffu, acc[t], off);
        }
        if (lane == 0) {
#pragma unroll
            for (int t = 0; t < 8; t++)
                g_h[(size_t)(tok0 + t)*48 + j] = tanhf(acc[t]);
        }
    }
}

// ---------------- kernel 2: qin/kin/vin = x + (xprev - x)*(lam + H@b^T), written as bf16x3 ------
__global__ void __launch_bounds__(256) mod_input_kernel(const float* __restrict__ x,
                                                        const float* __restrict__ qb, const float* __restrict__ ql,
                                                        const float* __restrict__ kb, const float* __restrict__ kl,
                                                        const float* __restrict__ vb, const float* __restrict__ vl) {
    const int which = blockIdx.y;                 // 0=q 1=k 2=v
    const int tok0  = blockIdx.x * 32;
    const float* b = (which == 0) ? qb : (which == 1) ? kb : vb;
    const float* l = (which == 0) ? ql : (which == 1) ? kl : vl;
    __nv_bfloat16* out = (which == 0) ? g_qcat : (which == 1) ? g_kcat : g_vcat;

    __shared__ float hs[32][LORA_D];
    const int tid = threadIdx.x;
    for (int i = tid; i < 32*LORA_D; i += 256) {
        int t = i >> 4, j = i & 15;
        hs[t][j] = g_h[(size_t)(tok0 + t)*48 + which*16 + j];
    }
    __syncthreads();

#pragma unroll
    for (int c = 0; c < 4; c++) {
        const int d = tid + c*256;
        float bv[LORA_D];
        const float4* brow = (const float4*)(b + (size_t)d * LORA_D);
#pragma unroll
        for (int q4 = 0; q4 < 4; q4++) {
            float4 w = brow[q4];
            bv[q4*4+0] = w.x; bv[q4*4+1] = w.y; bv[q4*4+2] = w.z; bv[q4*4+3] = w.w;
        }
        const float lam = l[d];
        float xprev = ((tok0 % TT) == 0) ? 0.f : x[(size_t)(tok0 - 1)*DIMN + d];
        for (int t = 0; t < 32; t++) {
            float xv = x[(size_t)(tok0 + t)*DIMN + d];
            float lr = lam;
#pragma unroll
            for (int j = 0; j < LORA_D; j++) lr += hs[t][j] * bv[j];
            float o = xv + (xprev - xv) * lr;
            xprev = xv;
            __nv_bfloat16 h = __float2bfloat16(o);
            float hf = __bfloat162float(h);
            __nv_bfloat16 lo = __float2bfloat16(o - hf);
            size_t base = (size_t)(tok0 + t)*KCAT + d;
            out[base]        = h;   // paired with W_hi
            out[base + 1024] = h;   // paired with W_lo
            out[base + 2048] = lo;  // paired with W_hi
        }
    }
}

// ---------------- kernel 2b: generic fp32 -> bf16x3 split ----------------
// mode 0 (activations): [hi | hi | lo].  mode 1 (weights): [hi | lo | hi]
__global__ void __launch_bounds__(256) split_bf16_kernel(const float* __restrict__ in,
                                                         __nv_bfloat16* __restrict__ out,
                                                         int mode) {
    const int idx = blockIdx.x * 256 + threadIdx.x;
    const int row = idx >> 10, col = idx & 1023;
    float v = in[idx];
    __nv_bfloat16 h = __float2bfloat16(v);
    float hf = __bfloat162float(h);
    __nv_bfloat16 lo = __float2bfloat16(v - hf);
    size_t base = (size_t)row * KCAT + col;
    out[base]        = h;
    out[base + 1024] = mode ? lo : h;
    out[base + 2048] = mode ? h  : lo;
}

// ---------------- kernel 3: C = Acat @ Wcat^T (+bias), bf16 tensor-core, K=3072 ----------------
// A: [4096 x 3072] bf16 row-major, W: [1024 x 3072] bf16 row-major, C: [4096 x 1024] fp32
__global__ void __launch_bounds__(256, 2) gemm_bf16cat_kernel(const __nv_bfloat16* __restrict__ A,
                                                              const __nv_bfloat16* __restrict__ W,
                                                              const float* __restrict__ bias,
                                                              float* __restrict__ C) {
    extern __shared__ char smem[];
    const unsigned int su = (unsigned int)__cvta_generic_to_shared(smem);
    const int tid  = threadIdx.x;
    const int lane = tid & 31, warp = tid >> 5;
    const int wm = warp & 1, wn = warp >> 1;           // warp grid 2(M) x 4(N), warp tile 64x32
    const int m0 = blockIdx.y * 128, n0 = blockIdx.x * 128;

    float c[4][4][4];
#pragma unroll
    for (int i = 0; i < 4; i++)
#pragma unroll
        for (int j = 0; j < 4; j++)
#pragma unroll
            for (int e = 0; e < 4; e++) c[i][j][e] = 0.f;

    const int crow = tid >> 3;      // 0..31 (row within tile, per e-step += 32)
    const int cc   = tid & 7;       // 16B chunk within 128B row

    auto issue = [&](int s) {
        const int k0 = s * 64;
        const unsigned int base = su + (unsigned int)((s & 1) * 32768);
#pragma unroll
        for (int e = 0; e < 4; e++) {
            const int row = crow + e * 32;
            const unsigned int sw = (unsigned int)((cc ^ (row & 7)) << 4);
            cpa16(base + row*128 + sw,          A + (size_t)(m0 + row)*KCAT + k0 + cc*8);
            cpa16(base + 16384 + row*128 + sw,  W + (size_t)(n0 + row)*KCAT + k0 + cc*8);
        }
        asm volatile("cp.async.commit_group;\n");
    };

    const int rA = wm*64 + (lane & 15);
    const int rB = wn*32 + (lane & 15);
    const int hi16 = lane >> 4;
    const int swA = rA & 7, swB = rB & 7;

    issue(0);
    issue(1);

    for (int it = 0; it < 48; it++) {
        if (it < 46) asm volatile("cp.async.wait_group 1;\n");
        else         asm volatile("cp.async.wait_group 0;\n");
        __syncthreads();

        const unsigned int Ab = su + (unsigned int)((it & 1) * 32768);
        const unsigned int Wb = Ab + 16384;

#pragma unroll
        for (int ks = 0; ks < 4; ks++) {
            unsigned int a[4][4], bfrag[2][4];
#pragma unroll
            for (int im = 0; im < 4; im++) {
                const int row = rA + im*16;
                ldsm4(Ab + row*128 + ((unsigned int)(((ks*2 + hi16) ^ swA)) << 4), a[im]);
            }
#pragma unroll
            for (int p = 0; p < 2; p++) {
                const int row = rB + p*16;
                ldsm4(Wb + row*128 + ((unsigned int)(((ks*2 + hi16) ^ swB)) << 4), bfrag[p]);
            }
#pragma unroll
            for (int im = 0; im < 4; im++)
#pragma unroll
                for (int in = 0; in < 4; in++) {
                    const unsigned int b0 = bfrag[in >> 1][in & 1];
                    const unsigned int b1 = bfrag[in >> 1][2 + (in & 1)];
                    mma16816(c[im][in], a[im], b0, b1);
                }
        }
        __syncthreads();
        if (it + 2 < 48) issue(it + 2);
    }

#pragma unroll
    for (int im = 0; im < 4; im++) {
        const int r0 = m0 + wm*64 + im*16 + (lane >> 2);
#pragma unroll
        for (int in = 0; in < 4; in++) {
            const int col = n0 + wn*32 + in*8 + 2*(lane & 3);
            float b0 = 0.f, b1 = 0.f;
            if (bias) { b0 = bias[col]; b1 = bias[col + 1]; }
            *(float2*)&C[(size_t)r0*1024 + col]       = make_float2(c[im][in][0] + b0, c[im][in][1] + b1);
            *(float2*)&C[(size_t)(r0 + 8)*1024 + col] = make_float2(c[im][in][2] + b0, c[im][in][3] + b1);
        }
    }
}

// ---------------- kernel 4: RoPE in-place on q and k ----------------
__global__ void __launch_bounds__(256) rope_kernel(float* __restrict__ q, float* __restrict__ k) {
    const int gid = blockIdx.x * 256 + threadIdx.x;
    float* p = (gid >> 21) ? k : q;
    const int e = gid & ((1 << 21) - 1);
    const int j = e & 31;
    const int h = (e >> 5) & 15;
    const int t = (e >> 9) & 1023;
    const int b = e >> 19;
    const size_t base = ((size_t)(b*TT + t))*DIMN + h*HDIM;

    float theta = 1.0f / powf(10000.0f, (float)j * (1.0f / 32.0f));
    float ang = (float)t * theta;
    float sn, cs;
    sincosf(ang, &sn, &cs);
    float xr = p[base + j];
    float xi = p[base + j + 32];
    p[base + j]      = xr*cs - xi*sn;
    p[base + j + 32] = xr*sn + xi*cs;
}

// ---------------- kernel 5: causal flash attention (fp32), out in (B,T,H*D) layout ----------
#define ATT_SMEM_BYTES ((2*64*68 + 64*64 + 64*65)*4)   // 67840

__global__ void __launch_bounds__(256) attention_kernel(const float* __restrict__ q,
                                                        const float* __restrict__ k,
                                                        const float* __restrict__ v,
                                                        float* __restrict__ o) {
    extern __shared__ float sm[];
    float* Qts = sm;
    float* Kts = sm + 64*68;
    float* Vs  = sm + 2*64*68;
    float* Ps  = sm + 2*64*68 + 64*64;

    const int tid = threadIdx.x;
    const int tx = tid & 15, ty = tid >> 4;
    const int qt = blockIdx.x;
    const int bh = blockIdx.y;
    const int b = bh >> 4, h = bh & 15;
    const int q0 = qt * 64;

    const float* qg = q + ((size_t)b*TT)*DIMN + h*HDIM;
    const float* kg = k + ((size_t)b*TT)*DIMN + h*HDIM;
    const float* vg = v + ((size_t)b*TT)*DIMN + h*HDIM;

#pragma unroll
    for (int e = 0; e < 16; e++) {
        int idx = tid + e*256;
        int r = idx >> 6, d = idx & 63;
        Qts[d*68 + r] = qg[(size_t)(q0 + r)*DIMN + d];
    }

    float m_i[4], l_i[4], oacc[4][4];
#pragma unroll
    for (int i = 0; i < 4; i++) {
        m_i[i] = -1e30f; l_i[i] = 0.f;
#pragma unroll
        for (int j = 0; j < 4; j++) oacc[i][j] = 0.f;
    }

    for (int kt = 0; kt <= qt; kt++) {
        const int k0 = kt * 64;
        __syncthreads();
#pragma unroll
        for (int e = 0; e < 16; e++) {
            int idx = tid + e*256;
            int r = idx >> 6, d = idx & 63;
            size_t gofs = (size_t)(k0 + r)*DIMN + d;
            Kts[d*68 + r] = kg[gofs];
            Vs[r*64 + d]  = vg[gofs];
        }
        __syncthreads();

        float s[4][4];
#pragma unroll
        for (int i = 0; i < 4; i++)
#pragma unroll
            for (int j = 0; j < 4; j++) s[i][j] = 0.f;

        for (int dd = 0; dd < 64; dd++) {
            float4 av = *(const float4*)&Qts[dd*68 + ty*4];
            float4 bv = *(const float4*)&Kts[dd*68 + tx*4];
            float aa[4] = {av.x, av.y, av.z, av.w};
            float bb[4] = {bv.x, bv.y, bv.z, bv.w};
#pragma unroll
            for (int i = 0; i < 4; i++)
#pragma unroll
                for (int j = 0; j < 4; j++) s[i][j] += aa[i] * bb[j];
        }

#pragma unroll
        for (int i = 0; i < 4; i++)
#pragma unroll
            for (int j = 0; j < 4; j++) s[i][j] *= 0.125f;

        if (kt == qt) {
#pragma unroll
            for (int i = 0; i < 4; i++)
#pragma unroll
                for (int j = 0; j < 4; j++)
                    if (tx*4 + j > ty*4 + i) s[i][j] = -1e30f;
        }

#pragma unroll
        for (int i = 0; i < 4; i++) {
            float mt = fmaxf(fmaxf(s[i][0], s[i][1]), fmaxf(s[i][2], s[i][3]));
#pragma unroll
            for (int off = 8; off; off >>= 1)
                mt = fmaxf(mt, __shfl_xor_sync(0xffffffffu, mt, off));
            float m_new = fmaxf(m_i[i], mt);
            float corr = __expf(m_i[i] - m_new);
            float rs = 0.f;
#pragma unroll
            for (int j = 0; j < 4; j++) {
                float pp = __expf(s[i][j] - m_new);
                s[i][j] = pp;
                rs += pp;
            }
#pragma unroll
            for (int off = 8; off; off >>= 1)
                rs += __shfl_xor_sync(0xffffffffu, rs, off);
            l_i[i] = l_i[i] * corr + rs;
            m_i[i] = m_new;
#pragma unroll
            for (int j = 0; j < 4; j++) oacc[i][j] *= corr;
        }

#pragma unroll
        for (int i = 0; i < 4; i++)
#pragma unroll
            for (int j = 0; j < 4; j++)
                Ps[(ty*4 + i)*65 + tx*4 + j] = s[i][j];
        __syncthreads();

        for (int cc = 0; cc < 64; cc++) {
            float4 vv = *(const float4*)&Vs[cc*64 + tx*4];
            float vj[4] = {vv.x, vv.y, vv.z, vv.w};
#pragma unroll
            for (int i = 0; i < 4; i++) {
                float pp = Ps[(ty*4 + i)*65 + cc];
#pragma unroll
                for (int j = 0; j < 4; j++) oacc[i][j] += pp * vj[j];
            }
        }
    }

    float* og = o + ((size_t)b*TT + q0)*DIMN + h*HDIM;
#pragma unroll
    for (int i = 0; i < 4; i++) {
        float inv = 1.0f / l_i[i];
#pragma unroll
        for (int j = 0; j < 4; j++)
            og[(size_t)(ty*4 + i)*DIMN + tx*4 + j] = oacc[i][j] * inv;
    }
}

// ---------------- launch ----------------
extern "C" void kernel_launch(void* const* d_in, const int* in_sizes, int n_in,
                              void* d_out, int out_size) {
    const float* x      = (const float*)d_in[0];
    const float* q_w    = (const float*)d_in[1];
    const float* k_w    = (const float*)d_in[2];
    const float* v_w    = (const float*)d_in[3];
    const float* q_a    = (const float*)d_in[4];
    const float* q_b    = (const float*)d_in[5];
    const float* q_l    = (const float*)d_in[6];
    const float* k_a    = (const float*)d_in[7];
    const float* k_b    = (const float*)d_in[8];
    const float* k_l    = (const float*)d_in[9];
    const float* v_a    = (const float*)d_in[10];
    const float* v_b    = (const float*)d_in[11];
    const float* v_l    = (const float*)d_in[12];
    const float* proj_w = (const float*)d_in[13];
    const float* proj_b = (const float*)d_in[14];
    float* out = (float*)d_out;

    __nv_bfloat16 *p_qcat, *p_kcat, *p_vcat, *p_wcat;
    float *p_q, *p_k, *p_v, *p_attn;
    cudaGetSymbolAddress((void**)&p_qcat, g_qcat);
    cudaGetSymbolAddress((void**)&p_kcat, g_kcat);
    cudaGetSymbolAddress((void**)&p_vcat, g_vcat);
    cudaGetSymbolAddress((void**)&p_wcat, g_wcat);
    cudaGetSymbolAddress((void**)&p_q,    g_q);
    cudaGetSymbolAddress((void**)&p_k,    g_k);
    cudaGetSymbolAddress((void**)&p_v,    g_v);
    cudaGetSymbolAddress((void**)&p_attn, g_attn);

    cudaFuncSetAttribute(attention_kernel,
                         cudaFuncAttributeMaxDynamicSharedMemorySize, ATT_SMEM_BYTES);
    cudaFuncSetAttribute(gemm_bf16cat_kernel,
                         cudaFuncAttributeMaxDynamicSharedMemorySize, 65536);

    const dim3 ggrid(8, 32);   // (N/128, M/128)

    lora_h_kernel<<<MTOK/8, 256>>>(x, q_a, k_a, v_a);
    mod_input_kernel<<<dim3(MTOK/32, 3), 256>>>(x, q_b, q_l, k_b, k_l, v_b, v_l);

    split_bf16_kernel<<<(DIMN*DIMN)/256, 256>>>(q_w, p_wcat, 1);
    gemm_bf16cat_kernel<<<ggrid, 256, 65536>>>(p_qcat, p_wcat, nullptr, p_q);

    split_bf16_kernel<<<(DIMN*DIMN)/256, 256>>>(k_w, p_wcat, 1);
    gemm_bf16cat_kernel<<<ggrid, 256, 65536>>>(p_kcat, p_wcat, nullptr, p_k);

    split_bf16_kernel<<<(DIMN*DIMN)/256, 256>>>(v_w, p_wcat, 1);
    gemm_bf16cat_kernel<<<ggrid, 256, 65536>>>(p_vcat, p_wcat, nullptr, p_v);

    rope_kernel<<<(2*MTOK*NHEADS*32)/256, 256>>>(p_q, p_k);
    attention_kernel<<<dim3(16, 64), 256, ATT_SMEM_BYTES>>>(p_q, p_k, p_v, p_attn);

    split_bf16_kernel<<<((size_t)MTOK*DIMN)/256, 256>>>(p_attn, p_qcat, 0);
    split_bf16_kernel<<<(DIMN*DIMN)/256, 256>>>(proj_w, p_wcat, 1);
    gemm_bf16cat_kernel<<<ggrid, 256, 65536>>>(p_qcat, p_wcat, proj_b, out);
}

// round 5
// speedup vs baseline: 2.6096x; 1.4509x over previous
#include <cuda_runtime.h>
#include <cuda_bf16.h>
#include <cuda_fp16.h>
#include <cstdint>
#include <stdint.h>
#include <math.h>

#define DIMN   1024
#define NHEADS 16
#define HDIM   64
#define LORA_D 16
#define BB     4
#define TT     1024
#define MTOK   (BB*TT)   // 4096
#define KCAT   3072      // 3x split concat K

// ---------------- scratch (static device allocations; no cudaMalloc) ----------------
__device__ float g_h[MTOK*48];
__device__ __nv_bfloat16 g_qcat[(size_t)MTOK*KCAT];
__device__ __nv_bfloat16 g_kcat[(size_t)MTOK*KCAT];
__device__ __nv_bfloat16 g_vcat[(size_t)MTOK*KCAT];
__device__ __nv_bfloat16 g_wcat[(size_t)DIMN*KCAT];
__device__ float g_q[MTOK*DIMN];
__device__ float g_k[MTOK*DIMN];
__device__ float g_v[MTOK*DIMN];
__device__ float g_attn[MTOK*DIMN];
// fp16 split arrays for attention, layout [b*16+h][t][64]
__device__ __half g_qh[(size_t)MTOK*DIMN];
__device__ __half g_ql[(size_t)MTOK*DIMN];
__device__ __half g_kh[(size_t)MTOK*DIMN];
__device__ __half g_kl[(size_t)MTOK*DIMN];
__device__ __half g_vh[(size_t)MTOK*DIMN];
__device__ __half g_vl[(size_t)MTOK*DIMN];

// ---------------- asm helpers ----------------
__device__ __forceinline__ void cpa16(unsigned int d, const void* s) {
    asm volatile("cp.async.cg.shared.global [%0], [%1], 16;\n" :: "r"(d), "l"(s));
}
__device__ __forceinline__ void ldsm4(unsigned int a, unsigned int* r) {
    asm volatile("ldmatrix.sync.aligned.m8n8.x4.shared.b16 {%0,%1,%2,%3}, [%4];\n"
        : "=r"(r[0]), "=r"(r[1]), "=r"(r[2]), "=r"(r[3]) : "r"(a));
}
__device__ __forceinline__ void ldsm4t(unsigned int a, unsigned int* r) {
    asm volatile("ldmatrix.sync.aligned.m8n8.x4.trans.shared.b16 {%0,%1,%2,%3}, [%4];\n"
        : "=r"(r[0]), "=r"(r[1]), "=r"(r[2]), "=r"(r[3]) : "r"(a));
}
__device__ __forceinline__ void mma16816(float* c, const unsigned int* a, unsigned int b0, unsigned int b1) {
    asm volatile("mma.sync.aligned.m16n8k16.row.col.f32.bf16.bf16.f32 "
        "{%0,%1,%2,%3},{%4,%5,%6,%7},{%8,%9},{%0,%1,%2,%3};\n"
        : "+f"(c[0]), "+f"(c[1]), "+f"(c[2]), "+f"(c[3])
        : "r"(a[0]), "r"(a[1]), "r"(a[2]), "r"(a[3]), "r"(b0), "r"(b1));
}
__device__ __forceinline__ void mmah(float* c, unsigned int a0, unsigned int a1,
                                     unsigned int a2, unsigned int a3,
                                     unsigned int b0, unsigned int b1) {
    asm volatile("mma.sync.aligned.m16n8k16.row.col.f32.f16.f16.f32 "
        "{%0,%1,%2,%3},{%4,%5,%6,%7},{%8,%9},{%0,%1,%2,%3};\n"
        : "+f"(c[0]), "+f"(c[1]), "+f"(c[2]), "+f"(c[3])
        : "r"(a0), "r"(a1), "r"(a2), "r"(a3), "r"(b0), "r"(b1));
}
__device__ __forceinline__ unsigned int ex2h2(unsigned int x) {
    unsigned int d;
    asm("ex2.approx.f16x2 %0, %1;" : "=r"(d) : "r"(x));
    return d;
}
__device__ __forceinline__ unsigned int cvt2h(float hi, float lo) {
    unsigned int d;
    asm("cvt.rn.f16x2.f32 %0, %1, %2;" : "=r"(d) : "f"(hi), "f"(lo));
    return d;
}

// ---------------- kernel 1: H = tanh(x @ Acat^T) ----------
__global__ void __launch_bounds__(256) lora_h_kernel(const float* __restrict__ x,
                                                     const float* __restrict__ qa,
                                                     const float* __restrict__ ka,
                                                     const float* __restrict__ va) {
    __shared__ float xs[8][DIMN];
    const int tok0 = blockIdx.x * 8;
    const int tid  = threadIdx.x;

    const float4* xg  = (const float4*)(x + (size_t)tok0 * DIMN);
    float4*       xs4 = (float4*)&xs[0][0];
#pragma unroll
    for (int i = 0; i < 8; i++) xs4[tid + i*256] = xg[tid + i*256];
    __syncthreads();

    const int warp = tid >> 5, lane = tid & 31;
#pragma unroll
    for (int jj = 0; jj < 6; jj++) {
        const int j = warp * 6 + jj;
        const float* a = (j < 16) ? (qa + j*DIMN)
                       : (j < 32) ? (ka + (j-16)*DIMN)
                                  : (va + (j-32)*DIMN);
        float acc[8];
#pragma unroll
        for (int t = 0; t < 8; t++) acc[t] = 0.f;
        for (int i = 0; i < 32; i++) {
            float av = a[lane + i*32];
#pragma unroll
            for (int t = 0; t < 8; t++) acc[t] += xs[t][lane + i*32] * av;
        }
#pragma unroll
        for (int off = 16; off; off >>= 1) {
#pragma unroll
            for (int t = 0; t < 8; t++)
                acc[t] += __shfl_xor_sync(0xffffffffu, acc[t], off);
        }
        if (lane == 0) {
#pragma unroll
            for (int t = 0; t < 8; t++)
                g_h[(size_t)(tok0 + t)*48 + j] = tanhf(acc[t]);
        }
    }
}

// ---------------- kernel 2: qin/kin/vin written as bf16x3 cat ------
__global__ void __launch_bounds__(256) mod_input_kernel(const float* __restrict__ x,
                                                        const float* __restrict__ qb, const float* __restrict__ ql,
                                                        const float* __restrict__ kb, const float* __restrict__ kl,
                                                        const float* __restrict__ vb, const float* __restrict__ vl) {
    const int which = blockIdx.y;
    const int tok0  = blockIdx.x * 32;
    const float* b = (which == 0) ? qb : (which == 1) ? kb : vb;
    const float* l = (which == 0) ? ql : (which == 1) ? kl : vl;
    __nv_bfloat16* out = (which == 0) ? g_qcat : (which == 1) ? g_kcat : g_vcat;

    __shared__ float hs[32][LORA_D];
    const int tid = threadIdx.x;
    for (int i = tid; i < 32*LORA_D; i += 256) {
        int t = i >> 4, j = i & 15;
        hs[t][j] = g_h[(size_t)(tok0 + t)*48 + which*16 + j];
    }
    __syncthreads();

#pragma unroll
    for (int c = 0; c < 4; c++) {
        const int d = tid + c*256;
        float bv[LORA_D];
        const float4* brow = (const float4*)(b + (size_t)d * LORA_D);
#pragma unroll
        for (int q4 = 0; q4 < 4; q4++) {
            float4 w = brow[q4];
            bv[q4*4+0] = w.x; bv[q4*4+1] = w.y; bv[q4*4+2] = w.z; bv[q4*4+3] = w.w;
        }
        const float lam = l[d];
        float xprev = ((tok0 % TT) == 0) ? 0.f : x[(size_t)(tok0 - 1)*DIMN + d];
        for (int t = 0; t < 32; t++) {
            float xv = x[(size_t)(tok0 + t)*DIMN + d];
            float lr = lam;
#pragma unroll
            for (int j = 0; j < LORA_D; j++) lr += hs[t][j] * bv[j];
            float o = xv + (xprev - xv) * lr;
            xprev = xv;
            __nv_bfloat16 h = __float2bfloat16(o);
            float hf = __bfloat162float(h);
            __nv_bfloat16 lo = __float2bfloat16(o - hf);
            size_t base = (size_t)(tok0 + t)*KCAT + d;
            out[base]        = h;
            out[base + 1024] = h;
            out[base + 2048] = lo;
        }
    }
}

// ---------------- kernel 2b: fp32 -> bf16x3 split ----------------
__global__ void __launch_bounds__(256) split_bf16_kernel(const float* __restrict__ in,
                                                         __nv_bfloat16* __restrict__ out,
                                                         int mode) {
    const int idx = blockIdx.x * 256 + threadIdx.x;
    const int row = idx >> 10, col = idx & 1023;
    float v = in[idx];
    __nv_bfloat16 h = __float2bfloat16(v);
    float hf = __bfloat162float(h);
    __nv_bfloat16 lo = __float2bfloat16(v - hf);
    size_t base = (size_t)row * KCAT + col;
    out[base]        = h;
    out[base + 1024] = mode ? lo : h;
    out[base + 2048] = mode ? h  : lo;
}

// ---------------- kernel 3: bf16 tensor-core GEMM, K=3072 ----------------
__global__ void __launch_bounds__(256, 2) gemm_bf16cat_kernel(const __nv_bfloat16* __restrict__ A,
                                                              const __nv_bfloat16* __restrict__ W,
                                                              const float* __restrict__ bias,
                                                              float* __restrict__ C) {
    extern __shared__ char smem[];
    const unsigned int su = (unsigned int)__cvta_generic_to_shared(smem);
    const int tid  = threadIdx.x;
    const int lane = tid & 31, warp = tid >> 5;
    const int wm = warp & 1, wn = warp >> 1;
    const int m0 = blockIdx.y * 128, n0 = blockIdx.x * 128;

    float c[4][4][4];
#pragma unroll
    for (int i = 0; i < 4; i++)
#pragma unroll
        for (int j = 0; j < 4; j++)
#pragma unroll
            for (int e = 0; e < 4; e++) c[i][j][e] = 0.f;

    const int crow = tid >> 3;
    const int cc   = tid & 7;

    auto issue = [&](int s) {
        const int k0 = s * 64;
        const unsigned int base = su + (unsigned int)((s & 1) * 32768);
#pragma unroll
        for (int e = 0; e < 4; e++) {
            const int row = crow + e * 32;
            const unsigned int sw = (unsigned int)((cc ^ (row & 7)) << 4);
            cpa16(base + row*128 + sw,          A + (size_t)(m0 + row)*KCAT + k0 + cc*8);
            cpa16(base + 16384 + row*128 + sw,  W + (size_t)(n0 + row)*KCAT + k0 + cc*8);
        }
        asm volatile("cp.async.commit_group;\n");
    };

    const int rA = wm*64 + (lane & 15);
    const int rB = wn*32 + (lane & 15);
    const int hi16 = lane >> 4;
    const int swA = rA & 7, swB = rB & 7;

    issue(0);
    issue(1);

    for (int it = 0; it < 48; it++) {
        if (it < 46) asm volatile("cp.async.wait_group 1;\n");
        else         asm volatile("cp.async.wait_group 0;\n");
        __syncthreads();

        const unsigned int Ab = su + (unsigned int)((it & 1) * 32768);
        const unsigned int Wb = Ab + 16384;

#pragma unroll
        for (int ks = 0; ks < 4; ks++) {
            unsigned int a[4][4], bfrag[2][4];
#pragma unroll
            for (int im = 0; im < 4; im++) {
                const int row = rA + im*16;
                ldsm4(Ab + row*128 + ((unsigned int)(((ks*2 + hi16) ^ swA)) << 4), a[im]);
            }
#pragma unroll
            for (int p = 0; p < 2; p++) {
                const int row = rB + p*16;
                ldsm4(Wb + row*128 + ((unsigned int)(((ks*2 + hi16) ^ swB)) << 4), bfrag[p]);
            }
#pragma unroll
            for (int im = 0; im < 4; im++)
#pragma unroll
                for (int in = 0; in < 4; in++) {
                    const unsigned int b0 = bfrag[in >> 1][in & 1];
                    const unsigned int b1 = bfrag[in >> 1][2 + (in & 1)];
                    mma16816(c[im][in], a[im], b0, b1);
                }
        }
        __syncthreads();
        if (it + 2 < 48) issue(it + 2);
    }

#pragma unroll
    for (int im = 0; im < 4; im++) {
        const int r0 = m0 + wm*64 + im*16 + (lane >> 2);
#pragma unroll
        for (int in = 0; in < 4; in++) {
            const int col = n0 + wn*32 + in*8 + 2*(lane & 3);
            float b0 = 0.f, b1 = 0.f;
            if (bias) { b0 = bias[col]; b1 = bias[col + 1]; }
            *(float2*)&C[(size_t)r0*1024 + col]       = make_float2(c[im][in][0] + b0, c[im][in][1] + b1);
            *(float2*)&C[(size_t)(r0 + 8)*1024 + col] = make_float2(c[im][in][2] + b0, c[im][in][3] + b1);
        }
    }
}

// ---------------- kernel 4: RoPE + fp16 hi/lo split to [bh][t][64] layout ----------------
__global__ void __launch_bounds__(256) rope_split_kernel(const float* __restrict__ q,
                                                         const float* __restrict__ k,
                                                         const float* __restrict__ v) {
    const int gid = blockIdx.x * 256 + threadIdx.x;     // 3 * 2^21 total
    const int stream = gid >> 21;
    const int e = gid & ((1 << 21) - 1);
    const int j = e & 31;
    const int t = (e >> 5) & 1023;
    const int h = (e >> 15) & 15;
    const int b = e >> 19;
    const size_t src = (size_t)(b*TT + t)*DIMN + h*HDIM;
    const size_t dst = ((size_t)(b*16 + h)*TT + t)*HDIM;

    if (stream < 2) {
        const float* s = stream ? k : q;
        __half* oh = stream ? g_kh : g_qh;
        __half* ol = stream ? g_kl : g_ql;
        float xr = s[src + j], xi = s[src + j + 32];
        float theta = 1.0f / powf(10000.0f, (float)j * (1.0f / 32.0f));
        float ang = (float)t * theta;
        float sn, cs;
        sincosf(ang, &sn, &cs);
        float yr = xr*cs - xi*sn;
        float yi = xr*sn + xi*cs;
        __half hr = __float2half_rn(yr);
        __half lr = __float2half_rn(yr - __half2float(hr));
        __half hi = __float2half_rn(yi);
        __half li = __float2half_rn(yi - __half2float(hi));
        oh[dst + j]      = hr;  ol[dst + j]      = lr;
        oh[dst + j + 32] = hi;  ol[dst + j + 32] = li;
    } else {
        float v0 = v[src + j], v1 = v[src + j + 32];
        __half h0 = __float2half_rn(v0);
        __half l0 = __float2half_rn(v0 - __half2float(h0));
        __half h1 = __float2half_rn(v1);
        __half l1 = __float2half_rn(v1 - __half2float(h1));
        g_vh[dst + j]      = h0;  g_vl[dst + j]      = l0;
        g_vh[dst + j + 32] = h1;  g_vl[dst + j + 32] = l1;
    }
}

// ---------------- kernel 5: tensor-core causal flash attention ----------------
// smem: Qh[64][64h] 8KB @0, Ql 8KB @8192; stage s: base 16384+s*32768:
//   Kh 8KB, Kl 8KB @+8192, V[128][64h] 16KB @+16384 (rows 0-63 hi, 64-127 lo)
#define ATTN_SMEM 81920

__global__ void __launch_bounds__(128, 2) attn_mma_kernel(float* __restrict__ o) {
    extern __shared__ char smx[];
    const unsigned int su = (unsigned int)__cvta_generic_to_shared(smx);
    const int tid = threadIdx.x, lane = tid & 31, warp = tid >> 5;
    const int bx = blockIdx.x;
    const int qt = 15 - (bx >> 6);          // heavy tiles first
    const int bh = bx & 63;
    const int q0 = qt * 64;
    const int nk = qt + 1;
    const size_t hb = (size_t)bh * (TT * HDIM);

    auto ldt = [&](unsigned int dstBase, const __half* g, int row0) {
#pragma unroll
        for (int e2 = 0; e2 < 4; e2++) {
            int idx = tid + e2*128;
            int r = idx >> 3, ch = idx & 7;
            cpa16(dstBase + (unsigned int)(r*128 + ((ch ^ (r & 7)) << 4)),
                  g + hb + (size_t)(row0 + r)*HDIM + ch*8);
        }
    };
    auto issue_kv = [&](int kt) {
        unsigned int base = su + 16384u + (unsigned int)((kt & 1) * 32768);
        ldt(base,               g_kh, kt*64);
        ldt(base + 8192u,       g_kl, kt*64);
        ldt(base + 16384u,      g_vh, kt*64);
        ldt(base + 16384u + 8192u, g_vl, kt*64);
        asm volatile("cp.async.commit_group;\n");
    };

    ldt(su, g_qh, q0);
    ldt(su + 8192u, g_ql, q0);
    asm volatile("cp.async.commit_group;\n");
    issue_kv(0);
    if (nk > 1) { issue_kv(1); asm volatile("cp.async.wait_group 1;\n"); }
    else        {              asm volatile("cp.async.wait_group 0;\n"); }
    __syncthreads();

    const int hi16 = lane >> 4;
    const int krow = lane & 15;
    const int wrow = warp*16 + (lane >> 2);

    // Q A-fragments (held in registers for whole block)
    unsigned int aq[2][4][4];
    {
        const int qrow = warp*16 + krow;
#pragma unroll
        for (int qb = 0; qb < 2; qb++)
#pragma unroll
            for (int ck = 0; ck < 4; ck++)
                ldsm4(su + (unsigned int)(qb*8192 + qrow*128 + (((2*ck + hi16) ^ (qrow & 7)) << 4)),
                      aq[qb][ck]);
    }

    float oacc[8][4], lacc[4];
#pragma unroll
    for (int j = 0; j < 8; j++)
#pragma unroll
        for (int e = 0; e < 4; e++) oacc[j][e] = 0.f;
#pragma unroll
    for (int e = 0; e < 4; e++) lacc[e] = 0.f;
    float m0 = -1e30f, m1 = -1e30f;

    const unsigned int ONES = 0x3C003C00u;

    for (int kt = 0; kt < nk; kt++) {
        const unsigned int sb = su + 16384u + (unsigned int)((kt & 1) * 32768);

        float c[8][4];
#pragma unroll
        for (int j = 0; j < 8; j++)
#pragma unroll
            for (int e = 0; e < 4; e++) c[j][e] = 0.f;

        // ---- S = Q'K'^T (3-term fp16 split, K=192) ----
#pragma unroll
        for (int seg = 0; seg < 3; seg++) {
            const unsigned int (*A)[4] = aq[seg == 2 ? 1 : 0];
            const unsigned int Kb = sb + (seg == 1 ? 8192u : 0u);
#pragma unroll
            for (int ck = 0; ck < 4; ck++) {
#pragma unroll
                for (int g = 0; g < 4; g++) {
                    unsigned int bq[4];
                    const int row = g*16 + krow;
                    ldsm4(Kb + (unsigned int)(row*128 + (((2*ck + hi16) ^ (row & 7)) << 4)), bq);
                    mmah(c[2*g],   A[ck][0], A[ck][1], A[ck][2], A[ck][3], bq[0], bq[2]);
                    mmah(c[2*g+1], A[ck][0], A[ck][1], A[ck][2], A[ck][3], bq[1], bq[3]);
                }
            }
        }

        // ---- softmax (base-2) ----
        const float alpha = 0.18033688011112042f;   // 0.125 * log2(e)
#pragma unroll
        for (int j = 0; j < 8; j++) {
            c[j][0] *= alpha; c[j][1] *= alpha; c[j][2] *= alpha; c[j][3] *= alpha;
        }
        if (kt == qt) {
#pragma unroll
            for (int j = 0; j < 8; j++) {
                const int cb = 8*j + 2*(lane & 3);
                if (cb     > wrow)     c[j][0] = -30000.f;
                if (cb + 1 > wrow)     c[j][1] = -30000.f;
                if (cb     > wrow + 8) c[j][2] = -30000.f;
                if (cb + 1 > wrow + 8) c[j][3] = -30000.f;
            }
        }
        float ml0 = -1e30f, ml1 = -1e30f;
#pragma unroll
        for (int j = 0; j < 8; j++) {
            ml0 = fmaxf(ml0, fmaxf(c[j][0], c[j][1]));
            ml1 = fmaxf(ml1, fmaxf(c[j][2], c[j][3]));
        }
#pragma unroll
        for (int off = 1; off <= 2; off <<= 1) {
            ml0 = fmaxf(ml0, __shfl_xor_sync(0xffffffffu, ml0, off));
            ml1 = fmaxf(ml1, __shfl_xor_sync(0xffffffffu, ml1, off));
        }
        const float mn0 = fmaxf(m0, ml0), mn1 = fmaxf(m1, ml1);
        const float cr0 = exp2f(m0 - mn0), cr1 = exp2f(m1 - mn1);
        m0 = mn0; m1 = mn1;

        unsigned int pf[2][8];
#pragma unroll
        for (int j = 0; j < 8; j++) {
            pf[0][j] = ex2h2(cvt2h(c[j][1] - m0, c[j][0] - m0));
            pf[1][j] = ex2h2(cvt2h(c[j][3] - m1, c[j][2] - m1));
        }
#pragma unroll
        for (int j = 0; j < 8; j++) {
            oacc[j][0] *= cr0; oacc[j][1] *= cr0;
            oacc[j][2] *= cr1; oacc[j][3] *= cr1;
        }
        lacc[0] *= cr0; lacc[1] *= cr0; lacc[2] *= cr1; lacc[3] *= cr1;

        // ---- O += P V  (2-term V split), l += P @ ones ----
#pragma unroll
        for (int kc = 0; kc < 4; kc++) {
            const unsigned int a0 = pf[0][2*kc],   a1 = pf[1][2*kc];
            const unsigned int a2 = pf[0][2*kc+1], a3 = pf[1][2*kc+1];
            mmah(lacc, a0, a1, a2, a3, ONES, ONES);
#pragma unroll
            for (int half = 0; half < 2; half++) {
                const int rbase = half*64 + kc*16 + krow;
                const unsigned int Vb = sb + 16384u;
#pragma unroll
                for (int jj = 0; jj < 4; jj++) {
                    unsigned int bv[4];
                    ldsm4t(Vb + (unsigned int)(rbase*128 + (((2*jj + hi16) ^ (rbase & 7)) << 4)), bv);
                    mmah(oacc[2*jj],   a0, a1, a2, a3, bv[0], bv[1]);
                    mmah(oacc[2*jj+1], a0, a1, a2, a3, bv[2], bv[3]);
                }
            }
        }

        if (kt + 1 < nk) {
            __syncthreads();
            if (kt + 2 < nk) {
                issue_kv(kt + 2);
                asm volatile("cp.async.wait_group 1;\n");
            } else {
                asm volatile("cp.async.wait_group 0;\n");
            }
            __syncthreads();
        }
    }

    // ---- epilogue: out = oacc / l, layout (B,T,H*D) ----
    const float inv0 = 1.f / lacc[0];
    const float inv1 = 1.f / lacc[2];
    const int b = bh >> 4, h = bh & 15;
    const int row0 = q0 + wrow;
    float* og = o + (size_t)(b*TT)*DIMN + h*HDIM;
#pragma unroll
    for (int j = 0; j < 8; j++) {
        const int col = 8*j + 2*(lane & 3);
        *(float2*)&og[(size_t)row0*DIMN + col] =
            make_float2(oacc[j][0]*inv0, oacc[j][1]*inv0);
        *(float2*)&og[(size_t)(row0 + 8)*DIMN + col] =
            make_float2(oacc[j][2]*inv1, oacc[j][3]*inv1);
    }
}

// ---------------- launch ----------------
extern "C" void kernel_launch(void* const* d_in, const int* in_sizes, int n_in,
                              void* d_out, int out_size) {
    const float* x      = (const float*)d_in[0];
    const float* q_w    = (const float*)d_in[1];
    const float* k_w    = (const float*)d_in[2];
    const float* v_w    = (const float*)d_in[3];
    const float* q_a    = (const float*)d_in[4];
    const float* q_b    = (const float*)d_in[5];
    const float* q_l    = (const float*)d_in[6];
    const float* k_a    = (const float*)d_in[7];
    const float* k_b    = (const float*)d_in[8];
    const float* k_l    = (const float*)d_in[9];
    const float* v_a    = (const float*)d_in[10];
    const float* v_b    = (const float*)d_in[11];
    const float* v_l    = (const float*)d_in[12];
    const float* proj_w = (const float*)d_in[13];
    const float* proj_b = (const float*)d_in[14];
    float* out = (float*)d_out;

    __nv_bfloat16 *p_qcat, *p_kcat, *p_vcat, *p_wcat;
    float *p_q, *p_k, *p_v, *p_attn;
    cudaGetSymbolAddress((void**)&p_qcat, g_qcat);
    cudaGetSymbolAddress((void**)&p_kcat, g_kcat);
    cudaGetSymbolAddress((void**)&p_vcat, g_vcat);
    cudaGetSymbolAddress((void**)&p_wcat, g_wcat);
    cudaGetSymbolAddress((void**)&p_q,    g_q);
    cudaGetSymbolAddress((void**)&p_k,    g_k);
    cudaGetSymbolAddress((void**)&p_v,    g_v);
    cudaGetSymbolAddress((void**)&p_attn, g_attn);

    cudaFuncSetAttribute(gemm_bf16cat_kernel,
                         cudaFuncAttributeMaxDynamicSharedMemorySize, 65536);
    cudaFuncSetAttribute(attn_mma_kernel,
                         cudaFuncAttributeMaxDynamicSharedMemorySize, ATTN_SMEM);

    const dim3 ggrid(8, 32);

    lora_h_kernel<<<MTOK/8, 256>>>(x, q_a, k_a, v_a);
    mod_input_kernel<<<dim3(MTOK/32, 3), 256>>>(x, q_b, q_l, k_b, k_l, v_b, v_l);

    split_bf16_kernel<<<(DIMN*DIMN)/256, 256>>>(q_w, p_wcat, 1);
    gemm_bf16cat_kernel<<<ggrid, 256, 65536>>>(p_qcat, p_wcat, nullptr, p_q);

    split_bf16_kernel<<<(DIMN*DIMN)/256, 256>>>(k_w, p_wcat, 1);
    gemm_bf16cat_kernel<<<ggrid, 256, 65536>>>(p_kcat, p_wcat, nullptr, p_k);

    split_bf16_kernel<<<(DIMN*DIMN)/256, 256>>>(v_w, p_wcat, 1);
    gemm_bf16cat_kernel<<<ggrid, 256, 65536>>>(p_vcat, p_wcat, nullptr, p_v);

    rope_split_kernel<<<(3*MTOK*NHEADS*32)/256, 256>>>(p_q, p_k, p_v);
    attn_mma_kernel<<<1024, 128, ATTN_SMEM>>>(p_attn);

    split_bf16_kernel<<<((size_t)MTOK*DIMN)/256, 256>>>(p_attn, p_qcat, 0);
    split_bf16_kernel<<<(DIMN*DIMN)/256, 256>>>(proj_w, p_wcat, 1);
    gemm_bf16cat_kernel<<<ggrid, 256, 65536>>>(p_qcat, p_wcat, proj_b, out);
}

// round 6
// speedup vs baseline: 2.6469x; 1.0143x over previous
#include <cuda_runtime.h>
#include <cuda_bf16.h>
#include <cuda_fp16.h>
#include <cstdint>
#include <stdint.h>
#include <math.h>

#define DIMN   1024
#define NHEADS 16
#define HDIM   64
#define LORA_D 16
#define BB     4
#define TT     1024
#define MTOK   (BB*TT)   // 4096
#define KCAT   3072      // 3x split concat K

// ---------------- scratch (static device allocations; no cudaMalloc) ----------------
__device__ float g_h[MTOK*48];
__device__ __nv_bfloat16 g_qcat[(size_t)MTOK*KCAT];
__device__ __nv_bfloat16 g_kcat[(size_t)MTOK*KCAT];
__device__ __nv_bfloat16 g_vcat[(size_t)MTOK*KCAT];
__device__ __nv_bfloat16 g_wq[(size_t)DIMN*KCAT];
__device__ __nv_bfloat16 g_wk[(size_t)DIMN*KCAT];
__device__ __nv_bfloat16 g_wv[(size_t)DIMN*KCAT];
__device__ __nv_bfloat16 g_wp[(size_t)DIMN*KCAT];
__device__ float g_q[MTOK*DIMN];
__device__ float g_k[MTOK*DIMN];
__device__ float g_v[MTOK*DIMN];
__device__ float g_attn[MTOK*DIMN];
// fp16 split arrays for attention, layout [b*16+h][t][64]
__device__ __half g_qh[(size_t)MTOK*DIMN];
__device__ __half g_ql[(size_t)MTOK*DIMN];
__device__ __half g_kh[(size_t)MTOK*DIMN];
__device__ __half g_kl[(size_t)MTOK*DIMN];
__device__ __half g_vh[(size_t)MTOK*DIMN];
__device__ __half g_vl[(size_t)MTOK*DIMN];

// ---------------- asm helpers ----------------
__device__ __forceinline__ void cpa16(unsigned int d, const void* s) {
    asm volatile("cp.async.cg.shared.global [%0], [%1], 16;\n" :: "r"(d), "l"(s));
}
__device__ __forceinline__ void ldsm4(unsigned int a, unsigned int* r) {
    asm volatile("ldmatrix.sync.aligned.m8n8.x4.shared.b16 {%0,%1,%2,%3}, [%4];\n"
        : "=r"(r[0]), "=r"(r[1]), "=r"(r[2]), "=r"(r[3]) : "r"(a));
}
__device__ __forceinline__ void ldsm4t(unsigned int a, unsigned int* r) {
    asm volatile("ldmatrix.sync.aligned.m8n8.x4.trans.shared.b16 {%0,%1,%2,%3}, [%4];\n"
        : "=r"(r[0]), "=r"(r[1]), "=r"(r[2]), "=r"(r[3]) : "r"(a));
}
__device__ __forceinline__ void mma16816(float* c, const unsigned int* a, unsigned int b0, unsigned int b1) {
    asm volatile("mma.sync.aligned.m16n8k16.row.col.f32.bf16.bf16.f32 "
        "{%0,%1,%2,%3},{%4,%5,%6,%7},{%8,%9},{%0,%1,%2,%3};\n"
        : "+f"(c[0]), "+f"(c[1]), "+f"(c[2]), "+f"(c[3])
        : "r"(a[0]), "r"(a[1]), "r"(a[2]), "r"(a[3]), "r"(b0), "r"(b1));
}
__device__ __forceinline__ void mmah(float* c, unsigned int a0, unsigned int a1,
                                     unsigned int a2, unsigned int a3,
                                     unsigned int b0, unsigned int b1) {
    asm volatile("mma.sync.aligned.m16n8k16.row.col.f32.f16.f16.f32 "
        "{%0,%1,%2,%3},{%4,%5,%6,%7},{%8,%9},{%0,%1,%2,%3};\n"
        : "+f"(c[0]), "+f"(c[1]), "+f"(c[2]), "+f"(c[3])
        : "r"(a0), "r"(a1), "r"(a2), "r"(a3), "r"(b0), "r"(b1));
}
__device__ __forceinline__ unsigned int ex2h2(unsigned int x) {
    unsigned int d;
    asm("ex2.approx.f16x2 %0, %1;" : "=r"(d) : "r"(x));
    return d;
}
__device__ __forceinline__ unsigned int cvt2h(float hi, float lo) {
    unsigned int d;
    asm("cvt.rn.f16x2.f32 %0, %1, %2;" : "=r"(d) : "f"(hi), "f"(lo));
    return d;
}

// ---------------- kernel 1: H = tanh(x @ Acat^T) ----------
__global__ void __launch_bounds__(256) lora_h_kernel(const float* __restrict__ x,
                                                     const float* __restrict__ qa,
                                                     const float* __restrict__ ka,
                                                     const float* __restrict__ va) {
    __shared__ float xs[8][DIMN];
    const int tok0 = blockIdx.x * 8;
    const int tid  = threadIdx.x;

    const float4* xg  = (const float4*)(x + (size_t)tok0 * DIMN);
    float4*       xs4 = (float4*)&xs[0][0];
#pragma unroll
    for (int i = 0; i < 8; i++) xs4[tid + i*256] = xg[tid + i*256];
    __syncthreads();

    const int warp = tid >> 5, lane = tid & 31;
#pragma unroll
    for (int jj = 0; jj < 6; jj++) {
        const int j = warp * 6 + jj;
        const float* a = (j < 16) ? (qa + j*DIMN)
                       : (j < 32) ? (ka + (j-16)*DIMN)
                                  : (va + (j-32)*DIMN);
        float acc[8];
#pragma unroll
        for (int t = 0; t < 8; t++) acc[t] = 0.f;
        for (int i = 0; i < 32; i++) {
            float av = a[lane + i*32];
#pragma unroll
            for (int t = 0; t < 8; t++) acc[t] += xs[t][lane + i*32] * av;
        }
#pragma unroll
        for (int off = 16; off; off >>= 1) {
#pragma unroll
            for (int t = 0; t < 8; t++)
                acc[t] += __shfl_xor_sync(0xffffffffu, acc[t], off);
        }
        if (lane == 0) {
#pragma unroll
            for (int t = 0; t < 8; t++)
                g_h[(size_t)(tok0 + t)*48 + j] = tanhf(acc[t]);
        }
    }
}

// ---------------- kernel 2: qin/kin/vin written as bf16x3 cat ------
__global__ void __launch_bounds__(256) mod_input_kernel(const float* __restrict__ x,
                                                        const float* __restrict__ qb, const float* __restrict__ ql,
                                                        const float* __restrict__ kb, const float* __restrict__ kl,
                                                        const float* __restrict__ vb, const float* __restrict__ vl) {
    const int which = blockIdx.y;
    const int tok0  = blockIdx.x * 32;
    const float* b = (which == 0) ? qb : (which == 1) ? kb : vb;
    const float* l = (which == 0) ? ql : (which == 1) ? kl : vl;
    __nv_bfloat16* out = (which == 0) ? g_qcat : (which == 1) ? g_kcat : g_vcat;

    __shared__ float hs[32][LORA_D];
    const int tid = threadIdx.x;
    for (int i = tid; i < 32*LORA_D; i += 256) {
        int t = i >> 4, j = i & 15;
        hs[t][j] = g_h[(size_t)(tok0 + t)*48 + which*16 + j];
    }
    __syncthreads();

#pragma unroll
    for (int c = 0; c < 4; c++) {
        const int d = tid + c*256;
        float bv[LORA_D];
        const float4* brow = (const float4*)(b + (size_t)d * LORA_D);
#pragma unroll
        for (int q4 = 0; q4 < 4; q4++) {
            float4 w = brow[q4];
            bv[q4*4+0] = w.x; bv[q4*4+1] = w.y; bv[q4*4+2] = w.z; bv[q4*4+3] = w.w;
        }
        const float lam = l[d];
        float xprev = ((tok0 % TT) == 0) ? 0.f : x[(size_t)(tok0 - 1)*DIMN + d];
        for (int t = 0; t < 32; t++) {
            float xv = x[(size_t)(tok0 + t)*DIMN + d];
            float lr = lam;
#pragma unroll
            for (int j = 0; j < LORA_D; j++) lr += hs[t][j] * bv[j];
            float o = xv + (xprev - xv) * lr;
            xprev = xv;
            __nv_bfloat16 h = __float2bfloat16(o);
            float hf = __bfloat162float(h);
            __nv_bfloat16 lo = __float2bfloat16(o - hf);
            size_t base = (size_t)(tok0 + t)*KCAT + d;
            out[base]        = h;
            out[base + 1024] = h;
            out[base + 2048] = lo;
        }
    }
}

// ---------------- kernel 2b: fp32 -> bf16x3 split ----------------
// mode 0 (activations): [hi | hi | lo].  mode 1 (weights): [hi | lo | hi]
__global__ void __launch_bounds__(256) split_bf16_kernel(const float* __restrict__ in,
                                                         __nv_bfloat16* __restrict__ out,
                                                         int mode) {
    const int idx = blockIdx.x * 256 + threadIdx.x;
    const int row = idx >> 10, col = idx & 1023;
    float v = in[idx];
    __nv_bfloat16 h = __float2bfloat16(v);
    float hf = __bfloat162float(h);
    __nv_bfloat16 lo = __float2bfloat16(v - hf);
    size_t base = (size_t)row * KCAT + col;
    out[base]        = h;
    out[base + 1024] = mode ? lo : h;
    out[base + 2048] = mode ? h  : lo;
}

// ---------------- kernel 2c: split all 4 weights at once ----------------
__global__ void __launch_bounds__(256) split_w4_kernel(const float* __restrict__ qw,
                                                       const float* __restrict__ kw,
                                                       const float* __restrict__ vw,
                                                       const float* __restrict__ pw) {
    const int which = blockIdx.y;
    const float* in = (which == 0) ? qw : (which == 1) ? kw : (which == 2) ? vw : pw;
    __nv_bfloat16* out = (which == 0) ? g_wq : (which == 1) ? g_wk : (which == 2) ? g_wv : g_wp;
    const int idx = blockIdx.x * 256 + threadIdx.x;
    const int row = idx >> 10, col = idx & 1023;
    float v = in[idx];
    __nv_bfloat16 h = __float2bfloat16(v);
    float hf = __bfloat162float(h);
    __nv_bfloat16 lo = __float2bfloat16(v - hf);
    size_t base = (size_t)row * KCAT + col;
    out[base]        = h;
    out[base + 1024] = lo;
    out[base + 2048] = h;
}

// ---------------- kernel 3: C = Acat @ Wcat^T (+bias), 256x128 tile, 3-stage ----------------
// A: [4096 x 3072] bf16, W: [1024 x 3072] bf16, C: [4096 x 1024] fp32
#define GSTAGE 49152            // 32KB A + 16KB B per stage
#define GSMEM  (3*GSTAGE)       // 147456

__global__ void __launch_bounds__(256, 1) gemm_bf16cat_kernel(const __nv_bfloat16* __restrict__ A,
                                                              const __nv_bfloat16* __restrict__ W,
                                                              const float* __restrict__ bias,
                                                              float* __restrict__ C) {
    extern __shared__ char smem[];
    const unsigned int su = (unsigned int)__cvta_generic_to_shared(smem);
    const int tid  = threadIdx.x;
    const int lane = tid & 31, warp = tid >> 5;
    const int wm = warp >> 1, wn = warp & 1;          // 4(M) x 2(N) warps, warp tile 64x64
    const int m0 = blockIdx.y * 256, n0 = blockIdx.x * 128;

    float acc[4][8][4];
#pragma unroll
    for (int i = 0; i < 4; i++)
#pragma unroll
        for (int j = 0; j < 8; j++)
#pragma unroll
            for (int e = 0; e < 4; e++) acc[i][j][e] = 0.f;

    const int crow = tid >> 3;          // 0..31
    const int cc   = tid & 7;

    auto issue = [&](int s) {
        const int k0 = s * 64;
        const unsigned int base = su + (unsigned int)((s % 3) * GSTAGE);
#pragma unroll
        for (int e = 0; e < 8; e++) {            // A: 256 rows
            const int row = crow + e * 32;
            const unsigned int sw = (unsigned int)((cc ^ (row & 7)) << 4);
            cpa16(base + row*128 + sw, A + (size_t)(m0 + row)*KCAT + k0 + cc*8);
        }
#pragma unroll
        for (int e = 0; e < 4; e++) {            // B: 128 rows
            const int row = crow + e * 32;
            const unsigned int sw = (unsigned int)((cc ^ (row & 7)) << 4);
            cpa16(base + 32768 + row*128 + sw, W + (size_t)(n0 + row)*KCAT + k0 + cc*8);
        }
        asm volatile("cp.async.commit_group;\n");
    };

    issue(0);
    issue(1);

    const int krow = lane & 15;
    const int hi16 = lane >> 4;

    for (int it = 0; it < 48; it++) {
        if (it < 47) asm volatile("cp.async.wait_group 1;\n");
        else         asm volatile("cp.async.wait_group 0;\n");
        __syncthreads();
        if (it + 2 < 48) issue(it + 2);

        const unsigned int Ab = su + (unsigned int)((it % 3) * GSTAGE);
        const unsigned int Wb = Ab + 32768;

#pragma unroll
        for (int ks = 0; ks < 4; ks++) {
            unsigned int a[4][4], b[4][4];
#pragma unroll
            for (int im = 0; im < 4; im++) {
                const int row = wm*64 + im*16 + krow;
                ldsm4(Ab + (unsigned int)(row*128 + (((2*ks + hi16) ^ (row & 7)) << 4)), a[im]);
            }
#pragma unroll
            for (int jn = 0; jn < 4; jn++) {
                const int row = wn*64 + jn*16 + krow;
                ldsm4(Wb + (unsigned int)(row*128 + (((2*ks + hi16) ^ (row & 7)) << 4)), b[jn]);
            }
#pragma unroll
            for (int im = 0; im < 4; im++)
#pragma unroll
                for (int j8 = 0; j8 < 8; j8++) {
                    const int jn = j8 >> 1, p = j8 & 1;
                    mma16816(acc[im][j8], a[im], b[jn][p], b[jn][2 + p]);
                }
        }
    }

#pragma unroll
    for (int im = 0; im < 4; im++) {
        const int r0 = m0 + wm*64 + im*16 + (lane >> 2);
#pragma unroll
        for (int j8 = 0; j8 < 8; j8++) {
            const int col = n0 + wn*64 + j8*8 + 2*(lane & 3);
            float b0 = 0.f, b1 = 0.f;
            if (bias) { b0 = bias[col]; b1 = bias[col + 1]; }
            *(float2*)&C[(size_t)r0*1024 + col]       = make_float2(acc[im][j8][0] + b0, acc[im][j8][1] + b1);
            *(float2*)&C[(size_t)(r0 + 8)*1024 + col] = make_float2(acc[im][j8][2] + b0, acc[im][j8][3] + b1);
        }
    }
}

// ---------------- kernel 4: RoPE + fp16 hi/lo split to [bh][t][64] layout ----------------
__global__ void __launch_bounds__(256) rope_split_kernel(const float* __restrict__ q,
                                                         const float* __restrict__ k,
                                                         const float* __restrict__ v) {
    const int gid = blockIdx.x * 256 + threadIdx.x;     // 3 * 2^21 total
    const int stream = gid >> 21;
    const int e = gid & ((1 << 21) - 1);
    const int j = e & 31;
    const int t = (e >> 5) & 1023;
    const int h = (e >> 15) & 15;
    const int b = e >> 19;
    const size_t src = (size_t)(b*TT + t)*DIMN + h*HDIM;
    const size_t dst = ((size_t)(b*16 + h)*TT + t)*HDIM;

    if (stream < 2) {
        const float* s = stream ? k : q;
        __half* oh = stream ? g_kh : g_qh;
        __half* ol = stream ? g_kl : g_ql;
        float xr = s[src + j], xi = s[src + j + 32];
        float theta = 1.0f / powf(10000.0f, (float)j * (1.0f / 32.0f));
        float ang = (float)t * theta;
        float sn, cs;
        sincosf(ang, &sn, &cs);
        float yr = xr*cs - xi*sn;
        float yi = xr*sn + xi*cs;
        __half hr = __float2half_rn(yr);
        __half lr = __float2half_rn(yr - __half2float(hr));
        __half hi = __float2half_rn(yi);
        __half li = __float2half_rn(yi - __half2float(hi));
        oh[dst + j]      = hr;  ol[dst + j]      = lr;
        oh[dst + j + 32] = hi;  ol[dst + j + 32] = li;
    } else {
        float v0 = v[src + j], v1 = v[src + j + 32];
        __half h0 = __float2half_rn(v0);
        __half l0 = __float2half_rn(v0 - __half2float(h0));
        __half h1 = __float2half_rn(v1);
        __half l1 = __float2half_rn(v1 - __half2float(h1));
        g_vh[dst + j]      = h0;  g_vl[dst + j]      = l0;
        g_vh[dst + j + 32] = h1;  g_vl[dst + j + 32] = l1;
    }
}

// ---------------- kernel 5: tensor-core causal flash attention ----------------
#define ATTN_SMEM 81920

__global__ void __launch_bounds__(128, 2) attn_mma_kernel(float* __restrict__ o) {
    extern __shared__ char smx[];
    const unsigned int su = (unsigned int)__cvta_generic_to_shared(smx);
    const int tid = threadIdx.x, lane = tid & 31, warp = tid >> 5;
    const int bx = blockIdx.x;
    const int qt = 15 - (bx >> 6);          // heavy tiles first
    const int bh = bx & 63;
    const int q0 = qt * 64;
    const int nk = qt + 1;
    const size_t hb = (size_t)bh * (TT * HDIM);

    auto ldt = [&](unsigned int dstBase, const __half* g, int row0) {
#pragma unroll
        for (int e2 = 0; e2 < 4; e2++) {
            int idx = tid + e2*128;
            int r = idx >> 3, ch = idx & 7;
            cpa16(dstBase + (unsigned int)(r*128 + ((ch ^ (r & 7)) << 4)),
                  g + hb + (size_t)(row0 + r)*HDIM + ch*8);
        }
    };
    auto issue_kv = [&](int kt) {
        unsigned int base = su + 16384u + (unsigned int)((kt & 1) * 32768);
        ldt(base,               g_kh, kt*64);
        ldt(base + 8192u,       g_kl, kt*64);
        ldt(base + 16384u,      g_vh, kt*64);
        ldt(base + 16384u + 8192u, g_vl, kt*64);
        asm volatile("cp.async.commit_group;\n");
    };

    ldt(su, g_qh, q0);
    ldt(su + 8192u, g_ql, q0);
    asm volatile("cp.async.commit_group;\n");
    issue_kv(0);
    if (nk > 1) { issue_kv(1); asm volatile("cp.async.wait_group 1;\n"); }
    else        {              asm volatile("cp.async.wait_group 0;\n"); }
    __syncthreads();

    const int hi16 = lane >> 4;
    const int krow = lane & 15;
    const int wrow = warp*16 + (lane >> 2);

    unsigned int aq[2][4][4];
    {
        const int qrow = warp*16 + krow;
#pragma unroll
        for (int qb = 0; qb < 2; qb++)
#pragma unroll
            for (int ck = 0; ck < 4; ck++)
                ldsm4(su + (unsigned int)(qb*8192 + qrow*128 + (((2*ck + hi16) ^ (qrow & 7)) << 4)),
                      aq[qb][ck]);
    }

    float oacc[8][4], lacc[4];
#pragma unroll
    for (int j = 0; j < 8; j++)
#pragma unroll
        for (int e = 0; e < 4; e++) oacc[j][e] = 0.f;
#pragma unroll
    for (int e = 0; e < 4; e++) lacc[e] = 0.f;
    float m0 = -1e30f, m1 = -1e30f;

    const unsigned int ONES = 0x3C003C00u;

    for (int kt = 0; kt < nk; kt++) {
        const unsigned int sb = su + 16384u + (unsigned int)((kt & 1) * 32768);

        float c[8][4];
#pragma unroll
        for (int j = 0; j < 8; j++)
#pragma unroll
            for (int e = 0; e < 4; e++) c[j][e] = 0.f;

#pragma unroll
        for (int seg = 0; seg < 3; seg++) {
            const unsigned int (*A)[4] = aq[seg == 2 ? 1 : 0];
            const unsigned int Kb = sb + (seg == 1 ? 8192u : 0u);
#pragma unroll
            for (int ck = 0; ck < 4; ck++) {
#pragma unroll
                for (int g = 0; g < 4; g++) {
                    unsigned int bq[4];
                    const int row = g*16 + krow;
                    ldsm4(Kb + (unsigned int)(row*128 + (((2*ck + hi16) ^ (row & 7)) << 4)), bq);
                    mmah(c[2*g],   A[ck][0], A[ck][1], A[ck][2], A[ck][3], bq[0], bq[2]);
                    mmah(c[2*g+1], A[ck][0], A[ck][1], A[ck][2], A[ck][3], bq[1], bq[3]);
                }
            }
        }

        const float alpha = 0.18033688011112042f;   // 0.125 * log2(e)
#pragma unroll
        for (int j = 0; j < 8; j++) {
            c[j][0] *= alpha; c[j][1] *= alpha; c[j][2] *= alpha; c[j][3] *= alpha;
        }
        if (kt == qt) {
#pragma unroll
            for (int j = 0; j < 8; j++) {
                const int cb = 8*j + 2*(lane & 3);
                if (cb     > wrow)     c[j][0] = -30000.f;
                if (cb + 1 > wrow)     c[j][1] = -30000.f;
                if (cb     > wrow + 8) c[j][2] = -30000.f;
                if (cb + 1 > wrow + 8) c[j][3] = -30000.f;
            }
        }
        float ml0 = -1e30f, ml1 = -1e30f;
#pragma unroll
        for (int j = 0; j < 8; j++) {
            ml0 = fmaxf(ml0, fmaxf(c[j][0], c[j][1]));
            ml1 = fmaxf(ml1, fmaxf(c[j][2], c[j][3]));
        }
#pragma unroll
        for (int off = 1; off <= 2; off <<= 1) {
            ml0 = fmaxf(ml0, __shfl_xor_sync(0xffffffffu, ml0, off));
            ml1 = fmaxf(ml1, __shfl_xor_sync(0xffffffffu, ml1, off));
        }
        const float mn0 = fmaxf(m0, ml0), mn1 = fmaxf(m1, ml1);
        const float cr0 = exp2f(m0 - mn0), cr1 = exp2f(m1 - mn1);
        m0 = mn0; m1 = mn1;

        unsigned int pf[2][8];
#pragma unroll
        for (int j = 0; j < 8; j++) {
            pf[0][j] = ex2h2(cvt2h(c[j][1] - m0, c[j][0] - m0));
            pf[1][j] = ex2h2(cvt2h(c[j][3] - m1, c[j][2] - m1));
        }
#pragma unroll
        for (int j = 0; j < 8; j++) {
            oacc[j][0] *= cr0; oacc[j][1] *= cr0;
            oacc[j][2] *= cr1; oacc[j][3] *= cr1;
        }
        lacc[0] *= cr0; lacc[1] *= cr0; lacc[2] *= cr1; lacc[3] *= cr1;

#pragma unroll
        for (int kc = 0; kc < 4; kc++) {
            const unsigned int a0 = pf[0][2*kc],   a1 = pf[1][2*kc];
            const unsigned int a2 = pf[0][2*kc+1], a3 = pf[1][2*kc+1];
            mmah(lacc, a0, a1, a2, a3, ONES, ONES);
#pragma unroll
            for (int half = 0; half < 2; half++) {
                const int rbase = half*64 + kc*16 + krow;
                const unsigned int Vb = sb + 16384u;
#pragma unroll
                for (int jj = 0; jj < 4; jj++) {
                    unsigned int bv[4];
                    ldsm4t(Vb + (unsigned int)(rbase*128 + (((2*jj + hi16) ^ (rbase & 7)) << 4)), bv);
                    mmah(oacc[2*jj],   a0, a1, a2, a3, bv[0], bv[1]);
                    mmah(oacc[2*jj+1], a0, a1, a2, a3, bv[2], bv[3]);
                }
            }
        }

        if (kt + 1 < nk) {
            __syncthreads();
            if (kt + 2 < nk) {
                issue_kv(kt + 2);
                asm volatile("cp.async.wait_group 1;\n");
            } else {
                asm volatile("cp.async.wait_group 0;\n");
            }
            __syncthreads();
        }
    }

    const float inv0 = 1.f / lacc[0];
    const float inv1 = 1.f / lacc[2];
    const int b = bh >> 4, h = bh & 15;
    const int row0 = q0 + wrow;
    float* og = o + (size_t)(b*TT)*DIMN + h*HDIM;
#pragma unroll
    for (int j = 0; j < 8; j++) {
        const int col = 8*j + 2*(lane & 3);
        *(float2*)&og[(size_t)row0*DIMN + col] =
            make_float2(oacc[j][0]*inv0, oacc[j][1]*inv0);
        *(float2*)&og[(size_t)(row0 + 8)*DIMN + col] =
            make_float2(oacc[j][2]*inv1, oacc[j][3]*inv1);
    }
}

// ---------------- launch ----------------
extern "C" void kernel_launch(void* const* d_in, const int* in_sizes, int n_in,
                              void* d_out, int out_size) {
    const float* x      = (const float*)d_in[0];
    const float* q_w    = (const float*)d_in[1];
    const float* k_w    = (const float*)d_in[2];
    const float* v_w    = (const float*)d_in[3];
    const float* q_a    = (const float*)d_in[4];
    const float* q_b    = (const float*)d_in[5];
    const float* q_l    = (const float*)d_in[6];
    const float* k_a    = (const float*)d_in[7];
    const float* k_b    = (const float*)d_in[8];
    const float* k_l    = (const float*)d_in[9];
    const float* v_a    = (const float*)d_in[10];
    const float* v_b    = (const float*)d_in[11];
    const float* v_l    = (const float*)d_in[12];
    const float* proj_w = (const float*)d_in[13];
    const float* proj_b = (const float*)d_in[14];
    float* out = (float*)d_out;

    __nv_bfloat16 *p_qcat, *p_kcat, *p_vcat, *p_wq, *p_wk, *p_wv, *p_wp;
    float *p_q, *p_k, *p_v, *p_attn;
    cudaGetSymbolAddress((void**)&p_qcat, g_qcat);
    cudaGetSymbolAddress((void**)&p_kcat, g_kcat);
    cudaGetSymbolAddress((void**)&p_vcat, g_vcat);
    cudaGetSymbolAddress((void**)&p_wq,   g_wq);
    cudaGetSymbolAddress((void**)&p_wk,   g_wk);
    cudaGetSymbolAddress((void**)&p_wv,   g_wv);
    cudaGetSymbolAddress((void**)&p_wp,   g_wp);
    cudaGetSymbolAddress((void**)&p_q,    g_q);
    cudaGetSymbolAddress((void**)&p_k,    g_k);
    cudaGetSymbolAddress((void**)&p_v,    g_v);
    cudaGetSymbolAddress((void**)&p_attn, g_attn);

    cudaFuncSetAttribute(gemm_bf16cat_kernel,
                         cudaFuncAttributeMaxDynamicSharedMemorySize, GSMEM);
    cudaFuncSetAttribute(attn_mma_kernel,
                         cudaFuncAttributeMaxDynamicSharedMemorySize, ATTN_SMEM);

    const dim3 ggrid(8, 16);   // (N/128, M/256)

    split_w4_kernel<<<dim3((DIMN*DIMN)/256, 4), 256>>>(q_w, k_w, v_w, proj_w);
    lora_h_kernel<<<MTOK/8, 256>>>(x, q_a, k_a, v_a);
    mod_input_kernel<<<dim3(MTOK/32, 3), 256>>>(x, q_b, q_l, k_b, k_l, v_b, v_l);

    gemm_bf16cat_kernel<<<ggrid, 256, GSMEM>>>(p_qcat, p_wq, nullptr, p_q);
    gemm_bf16cat_kernel<<<ggrid, 256, GSMEM>>>(p_kcat, p_wk, nullptr, p_k);
    gemm_bf16cat_kernel<<<ggrid, 256, GSMEM>>>(p_vcat, p_wv, nullptr, p_v);

    rope_split_kernel<<<(3*MTOK*NHEADS*32)/256, 256>>>(p_q, p_k, p_v);
    attn_mma_kernel<<<1024, 128, ATTN_SMEM>>>(p_attn);

    split_bf16_kernel<<<((size_t)MTOK*DIMN)/256, 256>>>(p_attn, p_qcat, 0);
    gemm_bf16cat_kernel<<<ggrid, 256, GSMEM>>>(p_qcat, p_wp, proj_b, out);
}

// round 8
// speedup vs baseline: 3.3655x; 1.2715x over previous
#include <cuda_runtime.h>
#include <cuda_bf16.h>
#include <cuda_fp16.h>
#include <cstdint>
#include <stdint.h>
#include <math.h>

#define DIMN   1024
#define NHEADS 16
#define HDIM   64
#define LORA_D 16
#define BB     4
#define TT     1024
#define MTOK   (BB*TT)   // 4096
#define KCAT   2048      // 2-term fp16 split concat K (acts)
#define NITER  32        // KCAT/64

// ---------------- scratch ----------------
__device__ float g_h[MTOK*48];
__device__ __half g_qcat[(size_t)MTOK*KCAT];   // [Ah | Al]
__device__ __half g_kcat[(size_t)MTOK*KCAT];
__device__ __half g_vcat[(size_t)MTOK*KCAT];
__device__ __half g_acat[(size_t)MTOK*KCAT];   // attn out split for proj
__device__ __half g_wq[(size_t)DIMN*DIMN];     // fp16 weights, K=1024
__device__ __half g_wk[(size_t)DIMN*DIMN];
__device__ __half g_wv[(size_t)DIMN*DIMN];
__device__ __half g_wp[(size_t)DIMN*DIMN];
__device__ float g_q[MTOK*DIMN];
__device__ float g_k[MTOK*DIMN];
__device__ float g_v[MTOK*DIMN];
__device__ float g_attn[MTOK*DIMN];
__device__ __half g_qh[(size_t)MTOK*DIMN];
__device__ __half g_ql[(size_t)MTOK*DIMN];
__device__ __half g_kh[(size_t)MTOK*DIMN];
__device__ __half g_kl[(size_t)MTOK*DIMN];
__device__ __half g_vh[(size_t)MTOK*DIMN];
__device__ __half g_vl[(size_t)MTOK*DIMN];

// ---------------- asm helpers ----------------
__device__ __forceinline__ void cpa16(unsigned int d, const void* s) {
    asm volatile("cp.async.cg.shared.global [%0], [%1], 16;\n" :: "r"(d), "l"(s));
}
__device__ __forceinline__ void ldsm4(unsigned int a, unsigned int* r) {
    asm volatile("ldmatrix.sync.aligned.m8n8.x4.shared.b16 {%0,%1,%2,%3}, [%4];\n"
        : "=r"(r[0]), "=r"(r[1]), "=r"(r[2]), "=r"(r[3]) : "r"(a));
}
__device__ __forceinline__ void ldsm4t(unsigned int a, unsigned int* r) {
    asm volatile("ldmatrix.sync.aligned.m8n8.x4.trans.shared.b16 {%0,%1,%2,%3}, [%4];\n"
        : "=r"(r[0]), "=r"(r[1]), "=r"(r[2]), "=r"(r[3]) : "r"(a));
}
__device__ __forceinline__ void mmah(float* c, unsigned int a0, unsigned int a1,
                                     unsigned int a2, unsigned int a3,
                                     unsigned int b0, unsigned int b1) {
    asm volatile("mma.sync.aligned.m16n8k16.row.col.f32.f16.f16.f32 "
        "{%0,%1,%2,%3},{%4,%5,%6,%7},{%8,%9},{%0,%1,%2,%3};\n"
        : "+f"(c[0]), "+f"(c[1]), "+f"(c[2]), "+f"(c[3])
        : "r"(a0), "r"(a1), "r"(a2), "r"(a3), "r"(b0), "r"(b1));
}
__device__ __forceinline__ unsigned int ex2h2(unsigned int x) {
    unsigned int d;
    asm("ex2.approx.f16x2 %0, %1;" : "=r"(d) : "r"(x));
    return d;
}
__device__ __forceinline__ unsigned int cvt2h(float hi, float lo) {
    unsigned int d;
    asm("cvt.rn.f16x2.f32 %0, %1, %2;" : "=r"(d) : "f"(hi), "f"(lo));
    return d;
}

// ---------------- kernel 1: H = tanh(x @ Acat^T) ----------
__global__ void __launch_bounds__(256) lora_h_kernel(const float* __restrict__ x,
                                                     const float* __restrict__ qa,
                                                     const float* __restrict__ ka,
                                                     const float* __restrict__ va) {
    __shared__ float xs[8][DIMN];
    const int tok0 = blockIdx.x * 8;
    const int tid  = threadIdx.x;

    const float4* xg  = (const float4*)(x + (size_t)tok0 * DIMN);
    float4*       xs4 = (float4*)&xs[0][0];
#pragma unroll
    for (int i = 0; i < 8; i++) xs4[tid + i*256] = xg[tid + i*256];
    __syncthreads();

    const int warp = tid >> 5, lane = tid & 31;
#pragma unroll
    for (int jj = 0; jj < 6; jj++) {
        const int j = warp * 6 + jj;
        const float* a = (j < 16) ? (qa + j*DIMN)
                       : (j < 32) ? (ka + (j-16)*DIMN)
                                  : (va + (j-32)*DIMN);
        float acc[8];
#pragma unroll
        for (int t = 0; t < 8; t++) acc[t] = 0.f;
        for (int i = 0; i < 32; i++) {
            float av = a[lane + i*32];
#pragma unroll
            for (int t = 0; t < 8; t++) acc[t] += xs[t][lane + i*32] * av;
        }
#pragma unroll
        for (int off = 16; off; off >>= 1) {
#pragma unroll
            for (int t = 0; t < 8; t++)
                acc[t] += __shfl_xor_sync(0xffffffffu, acc[t], off);
        }
        if (lane == 0) {
#pragma unroll
            for (int t = 0; t < 8; t++)
                g_h[(size_t)(tok0 + t)*48 + j] = tanhf(acc[t]);
        }
    }
}

// ---------------- kernel 2: mod inputs -> fp16 [hi|lo] cat ------
__global__ void __launch_bounds__(256) mod_input_kernel(const float* __restrict__ x,
                                                        const float* __restrict__ qb, const float* __restrict__ ql,
                                                        const float* __restrict__ kb, const float* __restrict__ kl,
                                                        const float* __restrict__ vb, const float* __restrict__ vl) {
    const int which = blockIdx.y;
    const int tok0  = blockIdx.x * 32;
    const float* b = (which == 0) ? qb : (which == 1) ? kb : vb;
    const float* l = (which == 0) ? ql : (which == 1) ? kl : vl;
    __half* out = (which == 0) ? g_qcat : (which == 1) ? g_kcat : g_vcat;

    __shared__ float hs[32][LORA_D];
    const int tid = threadIdx.x;
    for (int i = tid; i < 32*LORA_D; i += 256) {
        int t = i >> 4, j = i & 15;
        hs[t][j] = g_h[(size_t)(tok0 + t)*48 + which*16 + j];
    }
    __syncthreads();

#pragma unroll
    for (int c = 0; c < 4; c++) {
        const int d = tid + c*256;
        float bv[LORA_D];
        const float4* brow = (const float4*)(b + (size_t)d * LORA_D);
#pragma unroll
        for (int q4 = 0; q4 < 4; q4++) {
            float4 w = brow[q4];
            bv[q4*4+0] = w.x; bv[q4*4+1] = w.y; bv[q4*4+2] = w.z; bv[q4*4+3] = w.w;
        }
        const float lam = l[d];
        float xprev = ((tok0 % TT) == 0) ? 0.f : x[(size_t)(tok0 - 1)*DIMN + d];
        for (int t = 0; t < 32; t++) {
            float xv = x[(size_t)(tok0 + t)*DIMN + d];
            float lr = lam;
#pragma unroll
            for (int j = 0; j < LORA_D; j++) lr += hs[t][j] * bv[j];
            float o = xv + (xprev - xv) * lr;
            xprev = xv;
            __half h = __float2half_rn(o);
            __half lo = __float2half_rn(o - __half2float(h));
            size_t base = (size_t)(tok0 + t)*KCAT + d;
            out[base]        = h;    // Ah
            out[base + 1024] = lo;   // Al
        }
    }
}

// ---------------- kernel 2b: attn fp32 -> fp16 [hi|lo] cat ----------------
__global__ void __launch_bounds__(256) split_act_kernel(const float* __restrict__ in,
                                                        __half* __restrict__ out) {
    const int idx = blockIdx.x * 256 + threadIdx.x;
    const int row = idx >> 10, col = idx & 1023;
    float v = in[idx];
    __half h = __float2half_rn(v);
    __half lo = __float2half_rn(v - __half2float(h));
    size_t base = (size_t)row * KCAT + col;
    out[base]        = h;
    out[base + 1024] = lo;
}

// ---------------- kernel 2c: all 4 weights -> fp16 (single) ----------------
__global__ void __launch_bounds__(256) split_w4_kernel(const float* __restrict__ qw,
                                                       const float* __restrict__ kw,
                                                       const float* __restrict__ vw,
                                                       const float* __restrict__ pw) {
    const int which = blockIdx.y;
    const float* in = (which == 0) ? qw : (which == 1) ? kw : (which == 2) ? vw : pw;
    __half* out = (which == 0) ? g_wq : (which == 1) ? g_wk : (which == 2) ? g_wv : g_wp;
    const int idx = blockIdx.x * 256 + threadIdx.x;
    out[idx] = __float2half_rn(in[idx]);
}

// ---------------- kernel 3: C = Acat @ Wh^T (+bias), 256x128 tile, 3-stage, K=2048 ----------------
// A: [4096 x 2048] fp16, W: [1024 x 1024] fp16 (indexed mod 1024), C: [4096 x 1024] fp32
#define GSTAGE 49152            // 32KB A + 16KB B per stage
#define GSMEM  (3*GSTAGE)       // 147456

__global__ void __launch_bounds__(256, 1) gemm_fp16cat_kernel(const __half* __restrict__ A,
                                                              const __half* __restrict__ W,
                                                              const float* __restrict__ bias,
                                                              float* __restrict__ C) {
    extern __shared__ char smem[];
    const unsigned int su = (unsigned int)__cvta_generic_to_shared(smem);
    const int tid  = threadIdx.x;
    const int lane = tid & 31, warp = tid >> 5;
    const int wm = warp >> 1, wn = warp & 1;          // 4(M) x 2(N) warps, warp tile 64x64
    const int m0 = blockIdx.y * 256, n0 = blockIdx.x * 128;

    float acc[4][8][4];
#pragma unroll
    for (int i = 0; i < 4; i++)
#pragma unroll
        for (int j = 0; j < 8; j++)
#pragma unroll
            for (int e = 0; e < 4; e++) acc[i][j][e] = 0.f;

    const int crow = tid >> 3;          // 0..31
    const int cc   = tid & 7;

    auto issue = [&](int s) {
        const int k0 = s * 64;
        const int kw = k0 & 1023;                     // W reused for both segments
        const unsigned int base = su + (unsigned int)((s % 3) * GSTAGE);
#pragma unroll
        for (int e = 0; e < 8; e++) {                 // A: 256 rows
            const int row = crow + e * 32;
            const unsigned int sw = (unsigned int)((cc ^ (row & 7)) << 4);
            cpa16(base + row*128 + sw, A + (size_t)(m0 + row)*KCAT + k0 + cc*8);
        }
#pragma unroll
        for (int e = 0; e < 4; e++) {                 // B: 128 rows
            const int row = crow + e * 32;
            const unsigned int sw = (unsigned int)((cc ^ (row & 7)) << 4);
            cpa16(base + 32768 + row*128 + sw, W + (size_t)(n0 + row)*DIMN + kw + cc*8);
        }
        asm volatile("cp.async.commit_group;\n");
    };

    issue(0);
    issue(1);

    const int krow = lane & 15;
    const int hi16 = lane >> 4;

    for (int it = 0; it < NITER; it++) {
        if (it < NITER-1) asm volatile("cp.async.wait_group 1;\n");
        else              asm volatile("cp.async.wait_group 0;\n");
        __syncthreads();
        if (it + 2 < NITER) issue(it + 2);

        const unsigned int Ab = su + (unsigned int)((it % 3) * GSTAGE);
        const unsigned int Wb = Ab + 32768;

#pragma unroll
        for (int ks = 0; ks < 4; ks++) {
            unsigned int a[4][4], b[4][4];
#pragma unroll
            for (int im = 0; im < 4; im++) {
                const int row = wm*64 + im*16 + krow;
                ldsm4(Ab + (unsigned int)(row*128 + (((2*ks + hi16) ^ (row & 7)) << 4)), a[im]);
            }
#pragma unroll
            for (int jn = 0; jn < 4; jn++) {
                const int row = wn*64 + jn*16 + krow;
                ldsm4(Wb + (unsigned int)(row*128 + (((2*ks + hi16) ^ (row & 7)) << 4)), b[jn]);
            }
#pragma unroll
            for (int im = 0; im < 4; im++)
#pragma unroll
                for (int j8 = 0; j8 < 8; j8++) {
                    const int jn = j8 >> 1, p = j8 & 1;
                    mmah(acc[im][j8], a[im][0], a[im][1], a[im][2], a[im][3],
                         b[jn][p], b[jn][2 + p]);
                }
        }
    }

#pragma unroll
    for (int im = 0; im < 4; im++) {
        const int r0 = m0 + wm*64 + im*16 + (lane >> 2);
#pragma unroll
        for (int j8 = 0; j8 < 8; j8++) {
            const int col = n0 + wn*64 + j8*8 + 2*(lane & 3);
            float b0 = 0.f, b1 = 0.f;
            if (bias) { b0 = bias[col]; b1 = bias[col + 1]; }
            *(float2*)&C[(size_t)r0*1024 + col]       = make_float2(acc[im][j8][0] + b0, acc[im][j8][1] + b1);
            *(float2*)&C[(size_t)(r0 + 8)*1024 + col] = make_float2(acc[im][j8][2] + b0, acc[im][j8][3] + b1);
        }
    }
}

// ---------------- kernel 4: RoPE + fp16 hi/lo split ----------------
__global__ void __launch_bounds__(256) rope_split_kernel(const float* __restrict__ q,
                                                         const float* __restrict__ k,
                                                         const float* __restrict__ v) {
    const int gid = blockIdx.x * 256 + threadIdx.x;
    const int stream = gid >> 21;
    const int e = gid & ((1 << 21) - 1);
    const int j = e & 31;
    const int t = (e >> 5) & 1023;
    const int h = (e >> 15) & 15;
    const int b = e >> 19;
    const size_t src = (size_t)(b*TT + t)*DIMN + h*HDIM;
    const size_t dst = ((size_t)(b*16 + h)*TT + t)*HDIM;

    if (stream < 2) {
        const float* s = stream ? k : q;
        __half* oh = stream ? g_kh : g_qh;
        __half* ol = stream ? g_kl : g_ql;
        float xr = s[src + j], xi = s[src + j + 32];
        float theta = 1.0f / powf(10000.0f, (float)j * (1.0f / 32.0f));
        float ang = (float)t * theta;
        float sn, cs;
        sincosf(ang, &sn, &cs);
        float yr = xr*cs - xi*sn;
        float yi = xr*sn + xi*cs;
        __half hr = __float2half_rn(yr);
        __half lr = __float2half_rn(yr - __half2float(hr));
        __half hi = __float2half_rn(yi);
        __half li = __float2half_rn(yi - __half2float(hi));
        oh[dst + j]      = hr;  ol[dst + j]      = lr;
        oh[dst + j + 32] = hi;  ol[dst + j + 32] = li;
    } else {
        float v0 = v[src + j], v1 = v[src + j + 32];
        __half h0 = __float2half_rn(v0);
        __half l0 = __float2half_rn(v0 - __half2float(h0));
        __half h1 = __float2half_rn(v1);
        __half l1 = __float2half_rn(v1 - __half2float(h1));
        g_vh[dst + j]      = h0;  g_vl[dst + j]      = l0;
        g_vh[dst + j + 32] = h1;  g_vl[dst + j + 32] = l1;
    }
}

// ---------------- kernel 5: tensor-core causal flash attention ----------------
#define ATTN_SMEM 81920

__global__ void __launch_bounds__(128, 2) attn_mma_kernel(float* __restrict__ o) {
    extern __shared__ char smx[];
    const unsigned int su = (unsigned int)__cvta_generic_to_shared(smx);
    const int tid = threadIdx.x, lane = tid & 31, warp = tid >> 5;
    const int bx = blockIdx.x;
    const int qt = 15 - (bx >> 6);
    const int bh = bx & 63;
    const int q0 = qt * 64;
    const int nk = qt + 1;
    const size_t hb = (size_t)bh * (TT * HDIM);

    auto ldt = [&](unsigned int dstBase, const __half* g, int row0) {
#pragma unroll
        for (int e2 = 0; e2 < 4; e2++) {
            int idx = tid + e2*128;
            int r = idx >> 3, ch = idx & 7;
            cpa16(dstBase + (unsigned int)(r*128 + ((ch ^ (r & 7)) << 4)),
                  g + hb + (size_t)(row0 + r)*HDIM + ch*8);
        }
    };
    auto issue_kv = [&](int kt) {
        unsigned int base = su + 16384u + (unsigned int)((kt & 1) * 32768);
        ldt(base,               g_kh, kt*64);
        ldt(base + 8192u,       g_kl, kt*64);
        ldt(base + 16384u,      g_vh, kt*64);
        ldt(base + 16384u + 8192u, g_vl, kt*64);
        asm volatile("cp.async.commit_group;\n");
    };

    ldt(su, g_qh, q0);
    ldt(su + 8192u, g_ql, q0);
    asm volatile("cp.async.commit_group;\n");
    issue_kv(0);
    if (nk > 1) { issue_kv(1); asm volatile("cp.async.wait_group 1;\n"); }
    else        {              asm volatile("cp.async.wait_group 0;\n"); }
    __syncthreads();

    const int hi16 = lane >> 4;
    const int krow = lane & 15;
    const int wrow = warp*16 + (lane >> 2);

    unsigned int aq[2][4][4];
    {
        const int qrow = warp*16 + krow;
#pragma unroll
        for (int qb = 0; qb < 2; qb++)
#pragma unroll
            for (int ck = 0; ck < 4; ck++)
                ldsm4(su + (unsigned int)(qb*8192 + qrow*128 + (((2*ck + hi16) ^ (qrow & 7)) << 4)),
                      aq[qb][ck]);
    }

    float oacc[8][4], lacc[4];
#pragma unroll
    for (int j = 0; j < 8; j++)
#pragma unroll
        for (int e = 0; e < 4; e++) oacc[j][e] = 0.f;
#pragma unroll
    for (int e = 0; e < 4; e++) lacc[e] = 0.f;
    float m0 = -1e30f, m1 = -1e30f;

    const unsigned int ONES = 0x3C003C00u;

    for (int kt = 0; kt < nk; kt++) {
        const unsigned int sb = su + 16384u + (unsigned int)((kt & 1) * 32768);

        float c[8][4];
#pragma unroll
        for (int j = 0; j < 8; j++)
#pragma unroll
            for (int e = 0; e < 4; e++) c[j][e] = 0.f;

#pragma unroll
        for (int seg = 0; seg < 3; seg++) {
            const unsigned int (*Aa)[4] = aq[seg == 2 ? 1 : 0];
            const unsigned int Kb = sb + (seg == 1 ? 8192u : 0u);
#pragma unroll
            for (int ck = 0; ck < 4; ck++) {
#pragma unroll
                for (int g = 0; g < 4; g++) {
                    unsigned int bq[4];
                    const int row = g*16 + krow;
                    ldsm4(Kb + (unsigned int)(row*128 + (((2*ck + hi16) ^ (row & 7)) << 4)), bq);
                    mmah(c[2*g],   Aa[ck][0], Aa[ck][1], Aa[ck][2], Aa[ck][3], bq[0], bq[2]);
                    mmah(c[2*g+1], Aa[ck][0], Aa[ck][1], Aa[ck][2], Aa[ck][3], bq[1], bq[3]);
                }
            }
        }

        const float alpha = 0.18033688011112042f;
#pragma unroll
        for (int j = 0; j < 8; j++) {
            c[j][0] *= alpha; c[j][1] *= alpha; c[j][2] *= alpha; c[j][3] *= alpha;
        }
        if (kt == qt) {
#pragma unroll
            for (int j = 0; j < 8; j++) {
                const int cb = 8*j + 2*(lane & 3);
                if (cb     > wrow)     c[j][0] = -30000.f;
                if (cb + 1 > wrow)     c[j][1] = -30000.f;
                if (cb     > wrow + 8) c[j][2] = -30000.f;
                if (cb + 1 > wrow + 8) c[j][3] = -30000.f;
            }
        }
        float ml0 = -1e30f, ml1 = -1e30f;
#pragma unroll
        for (int j = 0; j < 8; j++) {
            ml0 = fmaxf(ml0, fmaxf(c[j][0], c[j][1]));
            ml1 = fmaxf(ml1, fmaxf(c[j][2], c[j][3]));
        }
#pragma unroll
        for (int off = 1; off <= 2; off <<= 1) {
            ml0 = fmaxf(ml0, __shfl_xor_sync(0xffffffffu, ml0, off));
            ml1 = fmaxf(ml1, __shfl_xor_sync(0xffffffffu, ml1, off));
        }
        const float mn0 = fmaxf(m0, ml0), mn1 = fmaxf(m1, ml1);
        const float cr0 = exp2f(m0 - mn0), cr1 = exp2f(m1 - mn1);
        m0 = mn0; m1 = mn1;

        unsigned int pf[2][8];
#pragma unroll
        for (int j = 0; j < 8; j++) {
            pf[0][j] = ex2h2(cvt2h(c[j][1] - m0, c[j][0] - m0));
            pf[1][j] = ex2h2(cvt2h(c[j][3] - m1, c[j][2] - m1));
        }
#pragma unroll
        for (int j = 0; j < 8; j++) {
            oacc[j][0] *= cr0; oacc[j][1] *= cr0;
            oacc[j][2] *= cr1; oacc[j][3] *= cr1;
        }
        lacc[0] *= cr0; lacc[1] *= cr0; lacc[2] *= cr1; lacc[3] *= cr1;

#pragma unroll
        for (int kc = 0; kc < 4; kc++) {
            const unsigned int a0 = pf[0][2*kc],   a1 = pf[1][2*kc];
            const unsigned int a2 = pf[0][2*kc+1], a3 = pf[1][2*kc+1];
            mmah(lacc, a0, a1, a2, a3, ONES, ONES);
#pragma unroll
            for (int half = 0; half < 2; half++) {
                const int rbase = half*64 + kc*16 + krow;
                const unsigned int Vb = sb + 16384u;
#pragma unroll
                for (int jj = 0; jj < 4; jj++) {
                    unsigned int bv[4];
                    ldsm4t(Vb + (unsigned int)(rbase*128 + (((2*jj + hi16) ^ (rbase & 7)) << 4)), bv);
                    mmah(oacc[2*jj],   a0, a1, a2, a3, bv[0], bv[1]);
                    mmah(oacc[2*jj+1], a0, a1, a2, a3, bv[2], bv[3]);
                }
            }
        }

        if (kt + 1 < nk) {
            __syncthreads();
            if (kt + 2 < nk) {
                issue_kv(kt + 2);
                asm volatile("cp.async.wait_group 1;\n");
            } else {
                asm volatile("cp.async.wait_group 0;\n");
            }
            __syncthreads();
        }
    }

    const float inv0 = 1.f / lacc[0];
    const float inv1 = 1.f / lacc[2];
    const int b = bh >> 4, h = bh & 15;
    const int row0 = q0 + wrow;
    float* og = o + (size_t)(b*TT)*DIMN + h*HDIM;
#pragma unroll
    for (int j = 0; j < 8; j++) {
        const int col = 8*j + 2*(lane & 3);
        *(float2*)&og[(size_t)row0*DIMN + col] =
            make_float2(oacc[j][0]*inv0, oacc[j][1]*inv0);
        *(float2*)&og[(size_t)(row0 + 8)*DIMN + col] =
            make_float2(oacc[j][2]*inv1, oacc[j][3]*inv1);
    }
}

// ---------------- launch ----------------
extern "C" void kernel_launch(void* const* d_in, const int* in_sizes, int n_in,
                              void* d_out, int out_size) {
    const float* x      = (const float*)d_in[0];
    const float* q_w    = (const float*)d_in[1];
    const float* k_w    = (const float*)d_in[2];
    const float* v_w    = (const float*)d_in[3];
    const float* q_a    = (const float*)d_in[4];
    const float* q_b    = (const float*)d_in[5];
    const float* q_l    = (const float*)d_in[6];
    const float* k_a    = (const float*)d_in[7];
    const float* k_b    = (const float*)d_in[8];
    const float* k_l    = (const float*)d_in[9];
    const float* v_a    = (const float*)d_in[10];
    const float* v_b    = (const float*)d_in[11];
    const float* v_l    = (const float*)d_in[12];
    const float* proj_w = (const float*)d_in[13];
    const float* proj_b = (const float*)d_in[14];
    float* out = (float*)d_out;

    __half *p_qcat, *p_kcat, *p_vcat, *p_acat, *p_wq, *p_wk, *p_wv, *p_wp;
    float *p_q, *p_k, *p_v, *p_attn;
    cudaGetSymbolAddress((void**)&p_qcat, g_qcat);
    cudaGetSymbolAddress((void**)&p_kcat, g_kcat);
    cudaGetSymbolAddress((void**)&p_vcat, g_vcat);
    cudaGetSymbolAddress((void**)&p_acat, g_acat);
    cudaGetSymbolAddress((void**)&p_wq,   g_wq);
    cudaGetSymbolAddress((void**)&p_wk,   g_wk);
    cudaGetSymbolAddress((void**)&p_wv,   g_wv);
    cudaGetSymbolAddress((void**)&p_wp,   g_wp);
    cudaGetSymbolAddress((void**)&p_q,    g_q);
    cudaGetSymbolAddress((void**)&p_k,    g_k);
    cudaGetSymbolAddress((void**)&p_v,    g_v);
    cudaGetSymbolAddress((void**)&p_attn, g_attn);

    cudaFuncSetAttribute(gemm_fp16cat_kernel,
                         cudaFuncAttributeMaxDynamicSharedMemorySize, GSMEM);
    cudaFuncSetAttribute(attn_mma_kernel,
                         cudaFuncAttributeMaxDynamicSharedMemorySize, ATTN_SMEM);

    const dim3 ggrid(8, 16);   // (N/128, M/256)

    split_w4_kernel<<<dim3((DIMN*DIMN)/256, 4), 256>>>(q_w, k_w, v_w, proj_w);
    lora_h_kernel<<<MTOK/8, 256>>>(x, q_a, k_a, v_a);
    mod_input_kernel<<<dim3(MTOK/32, 3), 256>>>(x, q_b, q_l, k_b, k_l, v_b, v_l);

    gemm_fp16cat_kernel<<<ggrid, 256, GSMEM>>>(p_qcat, p_wq, nullptr, p_q);
    gemm_fp16cat_kernel<<<ggrid, 256, GSMEM>>>(p_kcat, p_wk, nullptr, p_k);
    gemm_fp16cat_kernel<<<ggrid, 256, GSMEM>>>(p_vcat, p_wv, nullptr, p_v);

    rope_split_kernel<<<(3*MTOK*NHEADS*32)/256, 256>>>(p_q, p_k, p_v);
    attn_mma_kernel<<<1024, 128, ATTN_SMEM>>>(p_attn);

    split_act_kernel<<<((size_t)MTOK*DIMN)/256, 256>>>(p_attn, p_acat);
    gemm_fp16cat_kernel<<<ggrid, 256, GSMEM>>>(p_acat, p_wp, proj_b, out);
}

// round 9
// speedup vs baseline: 3.5287x; 1.0485x over previous
#include <cuda_runtime.h>
#include <cuda_bf16.h>
#include <cuda_fp16.h>
#include <cstdint>
#include <stdint.h>
#include <math.h>

#define DIMN   1024
#define NHEADS 16
#define HDIM   64
#define LORA_D 16
#define BB     4
#define TT     1024
#define MTOK   (BB*TT)   // 4096
#define KCAT   2048      // 2-term fp16 split concat K (acts)
#define NITER  32        // KCAT/64

// ---------------- scratch ----------------
__device__ float g_h[MTOK*48];
__device__ __half g_qcat[(size_t)MTOK*KCAT];   // [Ah | Al]
__device__ __half g_kcat[(size_t)MTOK*KCAT];
__device__ __half g_vcat[(size_t)MTOK*KCAT];
__device__ __half g_acat[(size_t)MTOK*KCAT];   // attn out split (written by attention)
__device__ __half g_wq[(size_t)DIMN*DIMN];     // fp16 weights, K=1024
__device__ __half g_wk[(size_t)DIMN*DIMN];
__device__ __half g_wv[(size_t)DIMN*DIMN];
__device__ __half g_wp[(size_t)DIMN*DIMN];
__device__ float g_q[MTOK*DIMN];
__device__ float g_k[MTOK*DIMN];
__device__ float g_v[MTOK*DIMN];
__device__ __half g_qh[(size_t)MTOK*DIMN];
__device__ __half g_ql[(size_t)MTOK*DIMN];
__device__ __half g_kh[(size_t)MTOK*DIMN];
__device__ __half g_vh[(size_t)MTOK*DIMN];
__device__ __half g_vl[(size_t)MTOK*DIMN];

// ---------------- asm helpers ----------------
__device__ __forceinline__ void cpa16(unsigned int d, const void* s) {
    asm volatile("cp.async.cg.shared.global [%0], [%1], 16;\n" :: "r"(d), "l"(s));
}
__device__ __forceinline__ void ldsm4(unsigned int a, unsigned int* r) {
    asm volatile("ldmatrix.sync.aligned.m8n8.x4.shared.b16 {%0,%1,%2,%3}, [%4];\n"
        : "=r"(r[0]), "=r"(r[1]), "=r"(r[2]), "=r"(r[3]) : "r"(a));
}
__device__ __forceinline__ void ldsm4t(unsigned int a, unsigned int* r) {
    asm volatile("ldmatrix.sync.aligned.m8n8.x4.trans.shared.b16 {%0,%1,%2,%3}, [%4];\n"
        : "=r"(r[0]), "=r"(r[1]), "=r"(r[2]), "=r"(r[3]) : "r"(a));
}
__device__ __forceinline__ void mmah(float* c, unsigned int a0, unsigned int a1,
                                     unsigned int a2, unsigned int a3,
                                     unsigned int b0, unsigned int b1) {
    asm volatile("mma.sync.aligned.m16n8k16.row.col.f32.f16.f16.f32 "
        "{%0,%1,%2,%3},{%4,%5,%6,%7},{%8,%9},{%0,%1,%2,%3};\n"
        : "+f"(c[0]), "+f"(c[1]), "+f"(c[2]), "+f"(c[3])
        : "r"(a0), "r"(a1), "r"(a2), "r"(a3), "r"(b0), "r"(b1));
}
__device__ __forceinline__ unsigned int ex2h2(unsigned int x) {
    unsigned int d;
    asm("ex2.approx.f16x2 %0, %1;" : "=r"(d) : "r"(x));
    return d;
}
__device__ __forceinline__ unsigned int cvt2h(float hi, float lo) {
    unsigned int d;
    asm("cvt.rn.f16x2.f32 %0, %1, %2;" : "=r"(d) : "f"(hi), "f"(lo));
    return d;
}

// ---------------- kernel 1: H = tanh(x @ Acat^T) ----------
__global__ void __launch_bounds__(256) lora_h_kernel(const float* __restrict__ x,
                                                     const float* __restrict__ qa,
                                                     const float* __restrict__ ka,
                                                     const float* __restrict__ va) {
    __shared__ float xs[8][DIMN];
    const int tok0 = blockIdx.x * 8;
    const int tid  = threadIdx.x;

    const float4* xg  = (const float4*)(x + (size_t)tok0 * DIMN);
    float4*       xs4 = (float4*)&xs[0][0];
#pragma unroll
    for (int i = 0; i < 8; i++) xs4[tid + i*256] = xg[tid + i*256];
    __syncthreads();

    const int warp = tid >> 5, lane = tid & 31;
#pragma unroll
    for (int jj = 0; jj < 6; jj++) {
        const int j = warp * 6 + jj;
        const float* a = (j < 16) ? (qa + j*DIMN)
                       : (j < 32) ? (ka + (j-16)*DIMN)
                                  : (va + (j-32)*DIMN);
        float acc[8];
#pragma unroll
        for (int t = 0; t < 8; t++) acc[t] = 0.f;
        for (int i = 0; i < 32; i++) {
            float av = a[lane + i*32];
#pragma unroll
            for (int t = 0; t < 8; t++) acc[t] += xs[t][lane + i*32] * av;
        }
#pragma unroll
        for (int off = 16; off; off >>= 1) {
#pragma unroll
            for (int t = 0; t < 8; t++)
                acc[t] += __shfl_xor_sync(0xffffffffu, acc[t], off);
        }
        if (lane == 0) {
#pragma unroll
            for (int t = 0; t < 8; t++)
                g_h[(size_t)(tok0 + t)*48 + j] = tanhf(acc[t]);
        }
    }
}

// ---------------- kernel 2: mod inputs -> fp16 [hi|lo] cat ------
__global__ void __launch_bounds__(256) mod_input_kernel(const float* __restrict__ x,
                                                        const float* __restrict__ qb, const float* __restrict__ ql,
                                                        const float* __restrict__ kb, const float* __restrict__ kl,
                                                        const float* __restrict__ vb, const float* __restrict__ vl) {
    const int which = blockIdx.y;
    const int tok0  = blockIdx.x * 32;
    const float* b = (which == 0) ? qb : (which == 1) ? kb : vb;
    const float* l = (which == 0) ? ql : (which == 1) ? kl : vl;
    __half* out = (which == 0) ? g_qcat : (which == 1) ? g_kcat : g_vcat;

    __shared__ float hs[32][LORA_D];
    const int tid = threadIdx.x;
    for (int i = tid; i < 32*LORA_D; i += 256) {
        int t = i >> 4, j = i & 15;
        hs[t][j] = g_h[(size_t)(tok0 + t)*48 + which*16 + j];
    }
    __syncthreads();

#pragma unroll
    for (int c = 0; c < 4; c++) {
        const int d = tid + c*256;
        float bv[LORA_D];
        const float4* brow = (const float4*)(b + (size_t)d * LORA_D);
#pragma unroll
        for (int q4 = 0; q4 < 4; q4++) {
            float4 w = brow[q4];
            bv[q4*4+0] = w.x; bv[q4*4+1] = w.y; bv[q4*4+2] = w.z; bv[q4*4+3] = w.w;
        }
        const float lam = l[d];
        float xprev = ((tok0 % TT) == 0) ? 0.f : x[(size_t)(tok0 - 1)*DIMN + d];
        for (int t = 0; t < 32; t++) {
            float xv = x[(size_t)(tok0 + t)*DIMN + d];
            float lr = lam;
#pragma unroll
            for (int j = 0; j < LORA_D; j++) lr += hs[t][j] * bv[j];
            float o = xv + (xprev - xv) * lr;
            xprev = xv;
            __half h = __float2half_rn(o);
            __half lo = __float2half_rn(o - __half2float(h));
            size_t base = (size_t)(tok0 + t)*KCAT + d;
            out[base]        = h;    // Ah
            out[base + 1024] = lo;   // Al
        }
    }
}

// ---------------- kernel 2c: all 4 weights -> fp16 ----------------
__global__ void __launch_bounds__(256) split_w4_kernel(const float* __restrict__ qw,
                                                       const float* __restrict__ kw,
                                                       const float* __restrict__ vw,
                                                       const float* __restrict__ pw) {
    const int which = blockIdx.y;
    const float* in = (which == 0) ? qw : (which == 1) ? kw : (which == 2) ? vw : pw;
    __half* out = (which == 0) ? g_wq : (which == 1) ? g_wk : (which == 2) ? g_wv : g_wp;
    const int idx = blockIdx.x * 256 + threadIdx.x;
    out[idx] = __float2half_rn(in[idx]);
}

// ---------------- GEMM body: C = Acat @ Wh^T (+bias), 256x128 tile, 3-stage, K=2048 ----------------
#define GSTAGE 49152
#define GSMEM  (3*GSTAGE)

__device__ __forceinline__ void gemm_body(const __half* __restrict__ A,
                                          const __half* __restrict__ W,
                                          const float* __restrict__ bias,
                                          float* __restrict__ C,
                                          char* smem, int bx, int by) {
    const unsigned int su = (unsigned int)__cvta_generic_to_shared(smem);
    const int tid  = threadIdx.x;
    const int lane = tid & 31, warp = tid >> 5;
    const int wm = warp >> 1, wn = warp & 1;
    const int m0 = by * 256, n0 = bx * 128;

    float acc[4][8][4];
#pragma unroll
    for (int i = 0; i < 4; i++)
#pragma unroll
        for (int j = 0; j < 8; j++)
#pragma unroll
            for (int e = 0; e < 4; e++) acc[i][j][e] = 0.f;

    const int crow = tid >> 3;
    const int cc   = tid & 7;

    auto issue = [&](int s) {
        const int k0 = s * 64;
        const int kw = k0 & 1023;
        const unsigned int base = su + (unsigned int)((s % 3) * GSTAGE);
#pragma unroll
        for (int e = 0; e < 8; e++) {
            const int row = crow + e * 32;
            const unsigned int sw = (unsigned int)((cc ^ (row & 7)) << 4);
            cpa16(base + row*128 + sw, A + (size_t)(m0 + row)*KCAT + k0 + cc*8);
        }
#pragma unroll
        for (int e = 0; e < 4; e++) {
            const int row = crow + e * 32;
            const unsigned int sw = (unsigned int)((cc ^ (row & 7)) << 4);
            cpa16(base + 32768 + row*128 + sw, W + (size_t)(n0 + row)*DIMN + kw + cc*8);
        }
        asm volatile("cp.async.commit_group;\n");
    };

    issue(0);
    issue(1);

    const int krow = lane & 15;
    const int hi16 = lane >> 4;

    for (int it = 0; it < NITER; it++) {
        if (it < NITER-1) asm volatile("cp.async.wait_group 1;\n");
        else              asm volatile("cp.async.wait_group 0;\n");
        __syncthreads();
        if (it + 2 < NITER) issue(it + 2);

        const unsigned int Ab = su + (unsigned int)((it % 3) * GSTAGE);
        const unsigned int Wb = Ab + 32768;

#pragma unroll
        for (int ks = 0; ks < 4; ks++) {
            unsigned int a[4][4], b[4][4];
#pragma unroll
            for (int im = 0; im < 4; im++) {
                const int row = wm*64 + im*16 + krow;
                ldsm4(Ab + (unsigned int)(row*128 + (((2*ks + hi16) ^ (row & 7)) << 4)), a[im]);
            }
#pragma unroll
            for (int jn = 0; jn < 4; jn++) {
                const int row = wn*64 + jn*16 + krow;
                ldsm4(Wb + (unsigned int)(row*128 + (((2*ks + hi16) ^ (row & 7)) << 4)), b[jn]);
            }
#pragma unroll
            for (int im = 0; im < 4; im++)
#pragma unroll
                for (int j8 = 0; j8 < 8; j8++) {
                    const int jn = j8 >> 1, p = j8 & 1;
                    mmah(acc[im][j8], a[im][0], a[im][1], a[im][2], a[im][3],
                         b[jn][p], b[jn][2 + p]);
                }
        }
    }

#pragma unroll
    for (int im = 0; im < 4; im++) {
        const int r0 = m0 + wm*64 + im*16 + (lane >> 2);
#pragma unroll
        for (int j8 = 0; j8 < 8; j8++) {
            const int col = n0 + wn*64 + j8*8 + 2*(lane & 3);
            float b0 = 0.f, b1 = 0.f;
            if (bias) { b0 = bias[col]; b1 = bias[col + 1]; }
            *(float2*)&C[(size_t)r0*1024 + col]       = make_float2(acc[im][j8][0] + b0, acc[im][j8][1] + b1);
            *(float2*)&C[(size_t)(r0 + 8)*1024 + col] = make_float2(acc[im][j8][2] + b0, acc[im][j8][3] + b1);
        }
    }
}

// batched q/k/v GEMM: z selects operands (device globals)
__global__ void __launch_bounds__(256, 1) gemm_qkv_kernel() {
    extern __shared__ char smem[];
    const int z = blockIdx.z;
    const __half* A = (z == 0) ? g_qcat : (z == 1) ? g_kcat : g_vcat;
    const __half* W = (z == 0) ? g_wq   : (z == 1) ? g_wk   : g_wv;
    float*       C = (z == 0) ? g_q    : (z == 1) ? g_k    : g_v;
    gemm_body(A, W, nullptr, C, smem, blockIdx.x, blockIdx.y);
}

__global__ void __launch_bounds__(256, 1) gemm_proj_kernel(const float* __restrict__ bias,
                                                           float* __restrict__ out) {
    extern __shared__ char smem[];
    gemm_body(g_acat, g_wp, bias, out, smem, blockIdx.x, blockIdx.y);
}

// ---------------- kernel 4: RoPE + fp16 split (k: hi only) ----------------
__global__ void __launch_bounds__(256) rope_split_kernel(const float* __restrict__ q,
                                                         const float* __restrict__ k,
                                                         const float* __restrict__ v) {
    const int gid = blockIdx.x * 256 + threadIdx.x;
    const int stream = gid >> 21;
    const int e = gid & ((1 << 21) - 1);
    const int j = e & 31;
    const int t = (e >> 5) & 1023;
    const int h = (e >> 15) & 15;
    const int b = e >> 19;
    const size_t src = (size_t)(b*TT + t)*DIMN + h*HDIM;
    const size_t dst = ((size_t)(b*16 + h)*TT + t)*HDIM;

    if (stream < 2) {
        const float* s = stream ? k : q;
        float xr = s[src + j], xi = s[src + j + 32];
        float theta = 1.0f / powf(10000.0f, (float)j * (1.0f / 32.0f));
        float ang = (float)t * theta;
        float sn, cs;
        sincosf(ang, &sn, &cs);
        float yr = xr*cs - xi*sn;
        float yi = xr*sn + xi*cs;
        __half hr = __float2half_rn(yr);
        __half hi = __float2half_rn(yi);
        if (stream == 0) {
            g_qh[dst + j]      = hr;
            g_qh[dst + j + 32] = hi;
            g_ql[dst + j]      = __float2half_rn(yr - __half2float(hr));
            g_ql[dst + j + 32] = __float2half_rn(yi - __half2float(hi));
        } else {
            g_kh[dst + j]      = hr;      // k: hi only (Q·Kl term dropped)
            g_kh[dst + j + 32] = hi;
        }
    } else {
        float v0 = v[src + j], v1 = v[src + j + 32];
        __half h0 = __float2half_rn(v0);
        __half h1 = __float2half_rn(v1);
        g_vh[dst + j]      = h0;  g_vl[dst + j]      = __float2half_rn(v0 - __half2float(h0));
        g_vh[dst + j + 32] = h1;  g_vl[dst + j + 32] = __float2half_rn(v1 - __half2float(h1));
    }
}

// ---------------- kernel 5: tensor-core causal flash attention ----------------
// smem: Qh 8KB @0, Ql 8KB @8192; stage s @16384+s*24576: Kh 8KB, V[128][64h] 16KB (hi rows 0-63, lo 64-127)
#define ATTN_SMEM 65536

__global__ void __launch_bounds__(128, 2) attn_mma_kernel() {
    extern __shared__ char smx[];
    const unsigned int su = (unsigned int)__cvta_generic_to_shared(smx);
    const int tid = threadIdx.x, lane = tid & 31, warp = tid >> 5;
    const int bx = blockIdx.x;
    const int qt = 15 - (bx >> 6);
    const int bh = bx & 63;
    const int q0 = qt * 64;
    const int nk = qt + 1;
    const size_t hb = (size_t)bh * (TT * HDIM);

    auto ldt = [&](unsigned int dstBase, const __half* g, int row0) {
#pragma unroll
        for (int e2 = 0; e2 < 4; e2++) {
            int idx = tid + e2*128;
            int r = idx >> 3, ch = idx & 7;
            cpa16(dstBase + (unsigned int)(r*128 + ((ch ^ (r & 7)) << 4)),
                  g + hb + (size_t)(row0 + r)*HDIM + ch*8);
        }
    };
    auto issue_kv = [&](int kt) {
        unsigned int base = su + 16384u + (unsigned int)((kt & 1) * 24576);
        ldt(base,           g_kh, kt*64);
        ldt(base + 8192u,   g_vh, kt*64);
        ldt(base + 16384u,  g_vl, kt*64);
        asm volatile("cp.async.commit_group;\n");
    };

    ldt(su, g_qh, q0);
    ldt(su + 8192u, g_ql, q0);
    asm volatile("cp.async.commit_group;\n");
    issue_kv(0);
    if (nk > 1) { issue_kv(1); asm volatile("cp.async.wait_group 1;\n"); }
    else        {              asm volatile("cp.async.wait_group 0;\n"); }
    __syncthreads();

    const int hi16 = lane >> 4;
    const int krow = lane & 15;
    const int wrow = warp*16 + (lane >> 2);

    unsigned int aq[2][4][4];
    {
        const int qrow = warp*16 + krow;
#pragma unroll
        for (int qb = 0; qb < 2; qb++)
#pragma unroll
            for (int ck = 0; ck < 4; ck++)
                ldsm4(su + (unsigned int)(qb*8192 + qrow*128 + (((2*ck + hi16) ^ (qrow & 7)) << 4)),
                      aq[qb][ck]);
    }

    float oacc[8][4], lacc[4];
#pragma unroll
    for (int j = 0; j < 8; j++)
#pragma unroll
        for (int e = 0; e < 4; e++) oacc[j][e] = 0.f;
#pragma unroll
    for (int e = 0; e < 4; e++) lacc[e] = 0.f;
    float m0 = -1e30f, m1 = -1e30f;

    const unsigned int ONES = 0x3C003C00u;

    for (int kt = 0; kt < nk; kt++) {
        const unsigned int sb = su + 16384u + (unsigned int)((kt & 1) * 24576);

        float c[8][4];
#pragma unroll
        for (int j = 0; j < 8; j++)
#pragma unroll
            for (int e = 0; e < 4; e++) c[j][e] = 0.f;

        // ---- S = (Qh + Ql) · Kh^T  (2-segment) ----
#pragma unroll
        for (int seg = 0; seg < 2; seg++) {
            const unsigned int (*Aa)[4] = aq[seg];
#pragma unroll
            for (int ck = 0; ck < 4; ck++) {
#pragma unroll
                for (int g = 0; g < 4; g++) {
                    unsigned int bq[4];
                    const int row = g*16 + krow;
                    ldsm4(sb + (unsigned int)(row*128 + (((2*ck + hi16) ^ (row & 7)) << 4)), bq);
                    mmah(c[2*g],   Aa[ck][0], Aa[ck][1], Aa[ck][2], Aa[ck][3], bq[0], bq[2]);
                    mmah(c[2*g+1], Aa[ck][0], Aa[ck][1], Aa[ck][2], Aa[ck][3], bq[1], bq[3]);
                }
            }
        }

        const float alpha = 0.18033688011112042f;   // 0.125 * log2(e)
#pragma unroll
        for (int j = 0; j < 8; j++) {
            c[j][0] *= alpha; c[j][1] *= alpha; c[j][2] *= alpha; c[j][3] *= alpha;
        }
        if (kt == qt) {
#pragma unroll
            for (int j = 0; j < 8; j++) {
                const int cb = 8*j + 2*(lane & 3);
                if (cb     > wrow)     c[j][0] = -30000.f;
                if (cb + 1 > wrow)     c[j][1] = -30000.f;
                if (cb     > wrow + 8) c[j][2] = -30000.f;
                if (cb + 1 > wrow + 8) c[j][3] = -30000.f;
            }
        }
        float ml0 = -1e30f, ml1 = -1e30f;
#pragma unroll
        for (int j = 0; j < 8; j++) {
            ml0 = fmaxf(ml0, fmaxf(c[j][0], c[j][1]));
            ml1 = fmaxf(ml1, fmaxf(c[j][2], c[j][3]));
        }
#pragma unroll
        for (int off = 1; off <= 2; off <<= 1) {
            ml0 = fmaxf(ml0, __shfl_xor_sync(0xffffffffu, ml0, off));
            ml1 = fmaxf(ml1, __shfl_xor_sync(0xffffffffu, ml1, off));
        }
        const float mn0 = fmaxf(m0, ml0), mn1 = fmaxf(m1, ml1);
        const float cr0 = exp2f(m0 - mn0), cr1 = exp2f(m1 - mn1);
        m0 = mn0; m1 = mn1;

        unsigned int pf[2][8];
#pragma unroll
        for (int j = 0; j < 8; j++) {
            pf[0][j] = ex2h2(cvt2h(c[j][1] - m0, c[j][0] - m0));
            pf[1][j] = ex2h2(cvt2h(c[j][3] - m1, c[j][2] - m1));
        }
#pragma unroll
        for (int j = 0; j < 8; j++) {
            oacc[j][0] *= cr0; oacc[j][1] *= cr0;
            oacc[j][2] *= cr1; oacc[j][3] *= cr1;
        }
        lacc[0] *= cr0; lacc[1] *= cr0; lacc[2] *= cr1; lacc[3] *= cr1;

#pragma unroll
        for (int kc = 0; kc < 4; kc++) {
            const unsigned int a0 = pf[0][2*kc],   a1 = pf[1][2*kc];
            const unsigned int a2 = pf[0][2*kc+1], a3 = pf[1][2*kc+1];
            mmah(lacc, a0, a1, a2, a3, ONES, ONES);
#pragma unroll
            for (int half = 0; half < 2; half++) {
                const int rbase = half*64 + kc*16 + krow;
                const unsigned int Vb = sb + 8192u;
#pragma unroll
                for (int jj = 0; jj < 4; jj++) {
                    unsigned int bv[4];
                    ldsm4t(Vb + (unsigned int)(rbase*128 + (((2*jj + hi16) ^ (rbase & 7)) << 4)), bv);
                    mmah(oacc[2*jj],   a0, a1, a2, a3, bv[0], bv[1]);
                    mmah(oacc[2*jj+1], a0, a1, a2, a3, bv[2], bv[3]);
                }
            }
        }

        if (kt + 1 < nk) {
            __syncthreads();
            if (kt + 2 < nk) {
                issue_kv(kt + 2);
                asm volatile("cp.async.wait_group 1;\n");
            } else {
                asm volatile("cp.async.wait_group 0;\n");
            }
            __syncthreads();
        }
    }

    // ---- epilogue: write fp16 [hi|lo] directly into g_acat ([tok][2048]) ----
    const float inv0 = 1.f / lacc[0];
    const float inv1 = 1.f / lacc[2];
    const int b = bh >> 4, h = bh & 15;
    const size_t tok0 = (size_t)b*TT + q0 + wrow;
#pragma unroll
    for (int j = 0; j < 8; j++) {
        const int col = 8*j + 2*(lane & 3);
        float a0 = oacc[j][0]*inv0, a1 = oacc[j][1]*inv0;
        float a2 = oacc[j][2]*inv1, a3 = oacc[j][3]*inv1;
        __half h0 = __float2half_rn(a0), h1 = __float2half_rn(a1);
        __half h2 = __float2half_rn(a2), h3 = __float2half_rn(a3);
        __half l0 = __float2half_rn(a0 - __half2float(h0));
        __half l1 = __float2half_rn(a1 - __half2float(h1));
        __half l2 = __float2half_rn(a2 - __half2float(h2));
        __half l3 = __float2half_rn(a3 - __half2float(h3));
        size_t base0 = tok0*KCAT + h*HDIM + col;
        size_t base1 = (tok0 + 8)*KCAT + h*HDIM + col;
        *(__half2*)&g_acat[base0]        = __halves2half2(h0, h1);
        *(__half2*)&g_acat[base0 + 1024] = __halves2half2(l0, l1);
        *(__half2*)&g_acat[base1]        = __halves2half2(h2, h3);
        *(__half2*)&g_acat[base1 + 1024] = __halves2half2(l2, l3);
    }
}

// ---------------- launch ----------------
extern "C" void kernel_launch(void* const* d_in, const int* in_sizes, int n_in,
                              void* d_out, int out_size) {
    const float* x      = (const float*)d_in[0];
    const float* q_w    = (const float*)d_in[1];
    const float* k_w    = (const float*)d_in[2];
    const float* v_w    = (const float*)d_in[3];
    const float* q_a    = (const float*)d_in[4];
    const float* q_b    = (const float*)d_in[5];
    const float* q_l    = (const float*)d_in[6];
    const float* k_a    = (const float*)d_in[7];
    const float* k_b    = (const float*)d_in[8];
    const float* k_l    = (const float*)d_in[9];
    const float* v_a    = (const float*)d_in[10];
    const float* v_b    = (const float*)d_in[11];
    const float* v_l    = (const float*)d_in[12];
    const float* proj_w = (const float*)d_in[13];
    const float* proj_b = (const float*)d_in[14];
    float* out = (float*)d_out;

    float *p_q, *p_k, *p_v;
    cudaGetSymbolAddress((void**)&p_q, g_q);
    cudaGetSymbolAddress((void**)&p_k, g_k);
    cudaGetSymbolAddress((void**)&p_v, g_v);

    cudaFuncSetAttribute(gemm_qkv_kernel,
                         cudaFuncAttributeMaxDynamicSharedMemorySize, GSMEM);
    cudaFuncSetAttribute(gemm_proj_kernel,
                         cudaFuncAttributeMaxDynamicSharedMemorySize, GSMEM);
    cudaFuncSetAttribute(attn_mma_kernel,
                         cudaFuncAttributeMaxDynamicSharedMemorySize, ATTN_SMEM);

    split_w4_kernel<<<dim3((DIMN*DIMN)/256, 4), 256>>>(q_w, k_w, v_w, proj_w);
    lora_h_kernel<<<MTOK/8, 256>>>(x, q_a, k_a, v_a);
    mod_input_kernel<<<dim3(MTOK/32, 3), 256>>>(x, q_b, q_l, k_b, k_l, v_b, v_l);

    gemm_qkv_kernel<<<dim3(8, 16, 3), 256, GSMEM>>>();

    rope_split_kernel<<<(3*MTOK*NHEADS*32)/256, 256>>>(p_q, p_k, p_v);
    attn_mma_kernel<<<1024, 128, ATTN_SMEM>>>();

    gemm_proj_kernel<<<dim3(8, 16), 256, GSMEM>>>(proj_b, out);
}

// round 10
// speedup vs baseline: 4.7432x; 1.3442x over previous
#include <cuda_runtime.h>
#include <cuda_bf16.h>
#include <cuda_fp16.h>
#include <cstdint>
#include <stdint.h>
#include <math.h>

#define DIMN   1024
#define NHEADS 16
#define HDIM   64
#define LORA_D 16
#define BB     4
#define TT     1024
#define MTOK   (BB*TT)   // 4096
#define KCATP  2048      // proj: 2-term fp16 split

// ---------------- scratch ----------------
__device__ float g_h[MTOK*48];
__device__ __half g_qcat[(size_t)MTOK*DIMN];   // qkv acts: single fp16 term
__device__ __half g_kcat[(size_t)MTOK*DIMN];
__device__ __half g_vcat[(size_t)MTOK*DIMN];
__device__ __half g_acat[(size_t)MTOK*KCATP];  // proj input [hi|lo], written by attention
__device__ __half g_wq[(size_t)DIMN*DIMN];
__device__ __half g_wk[(size_t)DIMN*DIMN];
__device__ __half g_wv[(size_t)DIMN*DIMN];
__device__ __half g_wp[(size_t)DIMN*DIMN];
__device__ float g_q[MTOK*DIMN];
__device__ float g_k[MTOK*DIMN];
__device__ float g_v[MTOK*DIMN];
__device__ __half g_qh[(size_t)MTOK*DIMN];
__device__ __half g_kh[(size_t)MTOK*DIMN];
__device__ __half g_vh[(size_t)MTOK*DIMN];

// ---------------- asm helpers ----------------
__device__ __forceinline__ void cpa16(unsigned int d, const void* s) {
    asm volatile("cp.async.cg.shared.global [%0], [%1], 16;\n" :: "r"(d), "l"(s));
}
__device__ __forceinline__ void ldsm4(unsigned int a, unsigned int* r) {
    asm volatile("ldmatrix.sync.aligned.m8n8.x4.shared.b16 {%0,%1,%2,%3}, [%4];\n"
        : "=r"(r[0]), "=r"(r[1]), "=r"(r[2]), "=r"(r[3]) : "r"(a));
}
__device__ __forceinline__ void ldsm4t(unsigned int a, unsigned int* r) {
    asm volatile("ldmatrix.sync.aligned.m8n8.x4.trans.shared.b16 {%0,%1,%2,%3}, [%4];\n"
        : "=r"(r[0]), "=r"(r[1]), "=r"(r[2]), "=r"(r[3]) : "r"(a));
}
__device__ __forceinline__ void mmah(float* c, unsigned int a0, unsigned int a1,
                                     unsigned int a2, unsigned int a3,
                                     unsigned int b0, unsigned int b1) {
    asm volatile("mma.sync.aligned.m16n8k16.row.col.f32.f16.f16.f32 "
        "{%0,%1,%2,%3},{%4,%5,%6,%7},{%8,%9},{%0,%1,%2,%3};\n"
        : "+f"(c[0]), "+f"(c[1]), "+f"(c[2]), "+f"(c[3])
        : "r"(a0), "r"(a1), "r"(a2), "r"(a3), "r"(b0), "r"(b1));
}
__device__ __forceinline__ unsigned int ex2h2(unsigned int x) {
    unsigned int d;
    asm("ex2.approx.f16x2 %0, %1;" : "=r"(d) : "r"(x));
    return d;
}
__device__ __forceinline__ unsigned int cvt2h(float hi, float lo) {
    unsigned int d;
    asm("cvt.rn.f16x2.f32 %0, %1, %2;" : "=r"(d) : "f"(hi), "f"(lo));
    return d;
}

// ---------------- kernel 1: H = tanh(x @ Acat^T) ----------
__global__ void __launch_bounds__(256) lora_h_kernel(const float* __restrict__ x,
                                                     const float* __restrict__ qa,
                                                     const float* __restrict__ ka,
                                                     const float* __restrict__ va) {
    __shared__ float xs[8][DIMN];
    const int tok0 = blockIdx.x * 8;
    const int tid  = threadIdx.x;

    const float4* xg  = (const float4*)(x + (size_t)tok0 * DIMN);
    float4*       xs4 = (float4*)&xs[0][0];
#pragma unroll
    for (int i = 0; i < 8; i++) xs4[tid + i*256] = xg[tid + i*256];
    __syncthreads();

    const int warp = tid >> 5, lane = tid & 31;
#pragma unroll
    for (int jj = 0; jj < 6; jj++) {
        const int j = warp * 6 + jj;
        const float* a = (j < 16) ? (qa + j*DIMN)
                       : (j < 32) ? (ka + (j-16)*DIMN)
                                  : (va + (j-32)*DIMN);
        float acc[8];
#pragma unroll
        for (int t = 0; t < 8; t++) acc[t] = 0.f;
        for (int i = 0; i < 32; i++) {
            float av = a[lane + i*32];
#pragma unroll
            for (int t = 0; t < 8; t++) acc[t] += xs[t][lane + i*32] * av;
        }
#pragma unroll
        for (int off = 16; off; off >>= 1) {
#pragma unroll
            for (int t = 0; t < 8; t++)
                acc[t] += __shfl_xor_sync(0xffffffffu, acc[t], off);
        }
        if (lane == 0) {
#pragma unroll
            for (int t = 0; t < 8; t++)
                g_h[(size_t)(tok0 + t)*48 + j] = tanhf(acc[t]);
        }
    }
}

// ---------------- kernel 2: mod inputs -> fp16 (single term) ------
__global__ void __launch_bounds__(256) mod_input_kernel(const float* __restrict__ x,
                                                        const float* __restrict__ qb, const float* __restrict__ ql,
                                                        const float* __restrict__ kb, const float* __restrict__ kl,
                                                        const float* __restrict__ vb, const float* __restrict__ vl) {
    const int which = blockIdx.y;
    const int tok0  = blockIdx.x * 32;
    const float* b = (which == 0) ? qb : (which == 1) ? kb : vb;
    const float* l = (which == 0) ? ql : (which == 1) ? kl : vl;
    __half* out = (which == 0) ? g_qcat : (which == 1) ? g_kcat : g_vcat;

    __shared__ float hs[32][LORA_D];
    const int tid = threadIdx.x;
    for (int i = tid; i < 32*LORA_D; i += 256) {
        int t = i >> 4, j = i & 15;
        hs[t][j] = g_h[(size_t)(tok0 + t)*48 + which*16 + j];
    }
    __syncthreads();

#pragma unroll
    for (int c = 0; c < 4; c++) {
        const int d = tid + c*256;
        float bv[LORA_D];
        const float4* brow = (const float4*)(b + (size_t)d * LORA_D);
#pragma unroll
        for (int q4 = 0; q4 < 4; q4++) {
            float4 w = brow[q4];
            bv[q4*4+0] = w.x; bv[q4*4+1] = w.y; bv[q4*4+2] = w.z; bv[q4*4+3] = w.w;
        }
        const float lam = l[d];
        float xprev = ((tok0 % TT) == 0) ? 0.f : x[(size_t)(tok0 - 1)*DIMN + d];
        for (int t = 0; t < 32; t++) {
            float xv = x[(size_t)(tok0 + t)*DIMN + d];
            float lr = lam;
#pragma unroll
            for (int j = 0; j < LORA_D; j++) lr += hs[t][j] * bv[j];
            float o = xv + (xprev - xv) * lr;
            xprev = xv;
            out[(size_t)(tok0 + t)*DIMN + d] = __float2half_rn(o);
        }
    }
}

// ---------------- kernel 2c: all 4 weights -> fp16 ----------------
__global__ void __launch_bounds__(256) split_w4_kernel(const float* __restrict__ qw,
                                                       const float* __restrict__ kw,
                                                       const float* __restrict__ vw,
                                                       const float* __restrict__ pw) {
    const int which = blockIdx.y;
    const float* in = (which == 0) ? qw : (which == 1) ? kw : (which == 2) ? vw : pw;
    __half* out = (which == 0) ? g_wq : (which == 1) ? g_wk : (which == 2) ? g_wv : g_wp;
    const int idx = blockIdx.x * 256 + threadIdx.x;
    out[idx] = __float2half_rn(in[idx]);
}

// ---------------- GEMM body: C = A @ W^T (+bias), 256x128 tile, 3-stage ----------------
#define GSTAGE 49152
#define GSMEM  (3*GSTAGE)

template<int KACT, int NIT>
__device__ __forceinline__ void gemm_body(const __half* __restrict__ A,
                                          const __half* __restrict__ W,
                                          const float* __restrict__ bias,
                                          float* __restrict__ C,
                                          char* smem, int bx, int by) {
    const unsigned int su = (unsigned int)__cvta_generic_to_shared(smem);
    const int tid  = threadIdx.x;
    const int lane = tid & 31, warp = tid >> 5;
    const int wm = warp >> 1, wn = warp & 1;
    const int m0 = by * 256, n0 = bx * 128;

    float acc[4][8][4];
#pragma unroll
    for (int i = 0; i < 4; i++)
#pragma unroll
        for (int j = 0; j < 8; j++)
#pragma unroll
            for (int e = 0; e < 4; e++) acc[i][j][e] = 0.f;

    const int crow = tid >> 3;
    const int cc   = tid & 7;

    auto issue = [&](int s) {
        const int k0 = s * 64;
        const int kw = k0 & 1023;
        const unsigned int base = su + (unsigned int)((s % 3) * GSTAGE);
#pragma unroll
        for (int e = 0; e < 8; e++) {
            const int row = crow + e * 32;
            const unsigned int sw = (unsigned int)((cc ^ (row & 7)) << 4);
            cpa16(base + row*128 + sw, A + (size_t)(m0 + row)*KACT + k0 + cc*8);
        }
#pragma unroll
        for (int e = 0; e < 4; e++) {
            const int row = crow + e * 32;
            const unsigned int sw = (unsigned int)((cc ^ (row & 7)) << 4);
            cpa16(base + 32768 + row*128 + sw, W + (size_t)(n0 + row)*DIMN + kw + cc*8);
        }
        asm volatile("cp.async.commit_group;\n");
    };

    issue(0);
    issue(1);

    const int krow = lane & 15;
    const int hi16 = lane >> 4;

    for (int it = 0; it < NIT; it++) {
        if (it < NIT-1) asm volatile("cp.async.wait_group 1;\n");
        else            asm volatile("cp.async.wait_group 0;\n");
        __syncthreads();
        if (it + 2 < NIT) issue(it + 2);

        const unsigned int Ab = su + (unsigned int)((it % 3) * GSTAGE);
        const unsigned int Wb = Ab + 32768;

#pragma unroll
        for (int ks = 0; ks < 4; ks++) {
            unsigned int a[4][4], b[4][4];
#pragma unroll
            for (int im = 0; im < 4; im++) {
                const int row = wm*64 + im*16 + krow;
                ldsm4(Ab + (unsigned int)(row*128 + (((2*ks + hi16) ^ (row & 7)) << 4)), a[im]);
            }
#pragma unroll
            for (int jn = 0; jn < 4; jn++) {
                const int row = wn*64 + jn*16 + krow;
                ldsm4(Wb + (unsigned int)(row*128 + (((2*ks + hi16) ^ (row & 7)) << 4)), b[jn]);
            }
#pragma unroll
            for (int im = 0; im < 4; im++)
#pragma unroll
                for (int j8 = 0; j8 < 8; j8++) {
                    const int jn = j8 >> 1, p = j8 & 1;
                    mmah(acc[im][j8], a[im][0], a[im][1], a[im][2], a[im][3],
                         b[jn][p], b[jn][2 + p]);
                }
        }
    }

#pragma unroll
    for (int im = 0; im < 4; im++) {
        const int r0 = m0 + wm*64 + im*16 + (lane >> 2);
#pragma unroll
        for (int j8 = 0; j8 < 8; j8++) {
            const int col = n0 + wn*64 + j8*8 + 2*(lane & 3);
            float b0 = 0.f, b1 = 0.f;
            if (bias) { b0 = bias[col]; b1 = bias[col + 1]; }
            *(float2*)&C[(size_t)r0*1024 + col]       = make_float2(acc[im][j8][0] + b0, acc[im][j8][1] + b1);
            *(float2*)&C[(size_t)(r0 + 8)*1024 + col] = make_float2(acc[im][j8][2] + b0, acc[im][j8][3] + b1);
        }
    }
}

// batched q/k/v GEMM (single-term, K=1024)
__global__ void __launch_bounds__(256, 1) gemm_qkv_kernel() {
    extern __shared__ char smem[];
    const int z = blockIdx.z;
    const __half* A = (z == 0) ? g_qcat : (z == 1) ? g_kcat : g_vcat;
    const __half* W = (z == 0) ? g_wq   : (z == 1) ? g_wk   : g_wv;
    float*       C = (z == 0) ? g_q    : (z == 1) ? g_k    : g_v;
    gemm_body<DIMN, 16>(A, W, nullptr, C, smem, blockIdx.x, blockIdx.y);
}

// proj GEMM (2-term, K=2048)
__global__ void __launch_bounds__(256, 1) gemm_proj_kernel(const float* __restrict__ bias,
                                                           float* __restrict__ out) {
    extern __shared__ char smem[];
    gemm_body<KCATP, 32>(g_acat, g_wp, bias, out, smem, blockIdx.x, blockIdx.y);
}

// ---------------- kernel 4: RoPE + fp16 (hi only) ----------------
__global__ void __launch_bounds__(256) rope_split_kernel(const float* __restrict__ q,
                                                         const float* __restrict__ k,
                                                         const float* __restrict__ v) {
    const int gid = blockIdx.x * 256 + threadIdx.x;
    const int stream = gid >> 21;
    const int e = gid & ((1 << 21) - 1);
    const int j = e & 31;
    const int t = (e >> 5) & 1023;
    const int h = (e >> 15) & 15;
    const int b = e >> 19;
    const size_t src = (size_t)(b*TT + t)*DIMN + h*HDIM;
    const size_t dst = ((size_t)(b*16 + h)*TT + t)*HDIM;

    if (stream < 2) {
        const float* s = stream ? k : q;
        __half* oh = stream ? g_kh : g_qh;
        float xr = s[src + j], xi = s[src + j + 32];
        float theta = 1.0f / powf(10000.0f, (float)j * (1.0f / 32.0f));
        float ang = (float)t * theta;
        float sn, cs;
        sincosf(ang, &sn, &cs);
        oh[dst + j]      = __float2half_rn(xr*cs - xi*sn);
        oh[dst + j + 32] = __float2half_rn(xr*sn + xi*cs);
    } else {
        g_vh[dst + j]      = __float2half_rn(v[src + j]);
        g_vh[dst + j + 32] = __float2half_rn(v[src + j + 32]);
    }
}

// ---------------- kernel 5: tensor-core causal flash attention (1-seg QK, 1-term PV) --------
// smem: Qh 8KB @0; stage s @8192+s*16384: Kh 8KB, Vh 8KB
#define ATTN_SMEM 40960

__global__ void __launch_bounds__(128, 3) attn_mma_kernel() {
    extern __shared__ char smx[];
    const unsigned int su = (unsigned int)__cvta_generic_to_shared(smx);
    const int tid = threadIdx.x, lane = tid & 31, warp = tid >> 5;
    const int bx = blockIdx.x;
    const int qt = 15 - (bx >> 6);
    const int bh = bx & 63;
    const int q0 = qt * 64;
    const int nk = qt + 1;
    const size_t hb = (size_t)bh * (TT * HDIM);

    auto ldt = [&](unsigned int dstBase, const __half* g, int row0) {
#pragma unroll
        for (int e2 = 0; e2 < 4; e2++) {
            int idx = tid + e2*128;
            int r = idx >> 3, ch = idx & 7;
            cpa16(dstBase + (unsigned int)(r*128 + ((ch ^ (r & 7)) << 4)),
                  g + hb + (size_t)(row0 + r)*HDIM + ch*8);
        }
    };
    auto issue_kv = [&](int kt) {
        unsigned int base = su + 8192u + (unsigned int)((kt & 1) * 16384);
        ldt(base,         g_kh, kt*64);
        ldt(base + 8192u, g_vh, kt*64);
        asm volatile("cp.async.commit_group;\n");
    };

    ldt(su, g_qh, q0);
    asm volatile("cp.async.commit_group;\n");
    issue_kv(0);
    if (nk > 1) { issue_kv(1); asm volatile("cp.async.wait_group 1;\n"); }
    else        {              asm volatile("cp.async.wait_group 0;\n"); }
    __syncthreads();

    const int hi16 = lane >> 4;
    const int krow = lane & 15;
    const int wrow = warp*16 + (lane >> 2);

    unsigned int aq[4][4];
    {
        const int qrow = warp*16 + krow;
#pragma unroll
        for (int ck = 0; ck < 4; ck++)
            ldsm4(su + (unsigned int)(qrow*128 + (((2*ck + hi16) ^ (qrow & 7)) << 4)), aq[ck]);
    }

    float oacc[8][4], lacc[4];
#pragma unroll
    for (int j = 0; j < 8; j++)
#pragma unroll
        for (int e = 0; e < 4; e++) oacc[j][e] = 0.f;
#pragma unroll
    for (int e = 0; e < 4; e++) lacc[e] = 0.f;
    float m0 = -1e30f, m1 = -1e30f;

    const unsigned int ONES = 0x3C003C00u;

    for (int kt = 0; kt < nk; kt++) {
        const unsigned int sb = su + 8192u + (unsigned int)((kt & 1) * 16384);

        float c[8][4];
#pragma unroll
        for (int j = 0; j < 8; j++)
#pragma unroll
            for (int e = 0; e < 4; e++) c[j][e] = 0.f;

        // ---- S = Qh · Kh^T ----
#pragma unroll
        for (int ck = 0; ck < 4; ck++) {
#pragma unroll
            for (int g = 0; g < 4; g++) {
                unsigned int bq[4];
                const int row = g*16 + krow;
                ldsm4(sb + (unsigned int)(row*128 + (((2*ck + hi16) ^ (row & 7)) << 4)), bq);
                mmah(c[2*g],   aq[ck][0], aq[ck][1], aq[ck][2], aq[ck][3], bq[0], bq[2]);
                mmah(c[2*g+1], aq[ck][0], aq[ck][1], aq[ck][2], aq[ck][3], bq[1], bq[3]);
            }
        }

        const float alpha = 0.18033688011112042f;   // 0.125 * log2(e)
#pragma unroll
        for (int j = 0; j < 8; j++) {
            c[j][0] *= alpha; c[j][1] *= alpha; c[j][2] *= alpha; c[j][3] *= alpha;
        }
        if (kt == qt) {
#pragma unroll
            for (int j = 0; j < 8; j++) {
                const int cb = 8*j + 2*(lane & 3);
                if (cb     > wrow)     c[j][0] = -30000.f;
                if (cb + 1 > wrow)     c[j][1] = -30000.f;
                if (cb     > wrow + 8) c[j][2] = -30000.f;
                if (cb + 1 > wrow + 8) c[j][3] = -30000.f;
            }
        }
        float ml0 = -1e30f, ml1 = -1e30f;
#pragma unroll
        for (int j = 0; j < 8; j++) {
            ml0 = fmaxf(ml0, fmaxf(c[j][0], c[j][1]));
            ml1 = fmaxf(ml1, fmaxf(c[j][2], c[j][3]));
        }
#pragma unroll
        for (int off = 1; off <= 2; off <<= 1) {
            ml0 = fmaxf(ml0, __shfl_xor_sync(0xffffffffu, ml0, off));
            ml1 = fmaxf(ml1, __shfl_xor_sync(0xffffffffu, ml1, off));
        }
        const float mn0 = fmaxf(m0, ml0), mn1 = fmaxf(m1, ml1);
        const float cr0 = exp2f(m0 - mn0), cr1 = exp2f(m1 - mn1);
        m0 = mn0; m1 = mn1;

        unsigned int pf[2][8];
#pragma unroll
        for (int j = 0; j < 8; j++) {
            pf[0][j] = ex2h2(cvt2h(c[j][1] - m0, c[j][0] - m0));
            pf[1][j] = ex2h2(cvt2h(c[j][3] - m1, c[j][2] - m1));
        }
#pragma unroll
        for (int j = 0; j < 8; j++) {
            oacc[j][0] *= cr0; oacc[j][1] *= cr0;
            oacc[j][2] *= cr1; oacc[j][3] *= cr1;
        }
        lacc[0] *= cr0; lacc[1] *= cr0; lacc[2] *= cr1; lacc[3] *= cr1;

        // ---- O += P Vh, l += P @ ones ----
        const unsigned int Vb = sb + 8192u;
#pragma unroll
        for (int kc = 0; kc < 4; kc++) {
            const unsigned int a0 = pf[0][2*kc],   a1 = pf[1][2*kc];
            const unsigned int a2 = pf[0][2*kc+1], a3 = pf[1][2*kc+1];
            mmah(lacc, a0, a1, a2, a3, ONES, ONES);
            const int rbase = kc*16 + krow;
#pragma unroll
            for (int jj = 0; jj < 4; jj++) {
                unsigned int bv[4];
                ldsm4t(Vb + (unsigned int)(rbase*128 + (((2*jj + hi16) ^ (rbase & 7)) << 4)), bv);
                mmah(oacc[2*jj],   a0, a1, a2, a3, bv[0], bv[1]);
                mmah(oacc[2*jj+1], a0, a1, a2, a3, bv[2], bv[3]);
            }
        }

        if (kt + 1 < nk) {
            __syncthreads();
            if (kt + 2 < nk) {
                issue_kv(kt + 2);
                asm volatile("cp.async.wait_group 1;\n");
            } else {
                asm volatile("cp.async.wait_group 0;\n");
            }
            __syncthreads();
        }
    }

    // ---- epilogue: write fp16 [hi|lo] into g_acat ([tok][2048]) ----
    const float inv0 = 1.f / lacc[0];
    const float inv1 = 1.f / lacc[2];
    const int b = bh >> 4, h = bh & 15;
    const size_t tok0 = (size_t)b*TT + q0 + wrow;
#pragma unroll
    for (int j = 0; j < 8; j++) {
        const int col = 8*j + 2*(lane & 3);
        float a0 = oacc[j][0]*inv0, a1 = oacc[j][1]*inv0;
        float a2 = oacc[j][2]*inv1, a3 = oacc[j][3]*inv1;
        __half h0 = __float2half_rn(a0), h1 = __float2half_rn(a1);
        __half h2 = __float2half_rn(a2), h3 = __float2half_rn(a3);
        __half l0 = __float2half_rn(a0 - __half2float(h0));
        __half l1 = __float2half_rn(a1 - __half2float(h1));
        __half l2 = __float2half_rn(a2 - __half2float(h2));
        __half l3 = __float2half_rn(a3 - __half2float(h3));
        size_t base0 = tok0*KCATP + h*HDIM + col;
        size_t base1 = (tok0 + 8)*KCATP + h*HDIM + col;
        *(__half2*)&g_acat[base0]        = __halves2half2(h0, h1);
        *(__half2*)&g_acat[base0 + 1024] = __halves2half2(l0, l1);
        *(__half2*)&g_acat[base1]        = __halves2half2(h2, h3);
        *(__half2*)&g_acat[base1 + 1024] = __halves2half2(l2, l3);
    }
}

// ---------------- launch ----------------
extern "C" void kernel_launch(void* const* d_in, const int* in_sizes, int n_in,
                              void* d_out, int out_size) {
    const float* x      = (const float*)d_in[0];
    const float* q_w    = (const float*)d_in[1];
    const float* k_w    = (const float*)d_in[2];
    const float* v_w    = (const float*)d_in[3];
    const float* q_a    = (const float*)d_in[4];
    const float* q_b    = (const float*)d_in[5];
    const float* q_l    = (const float*)d_in[6];
    const float* k_a    = (const float*)d_in[7];
    const float* k_b    = (const float*)d_in[8];
    const float* k_l    = (const float*)d_in[9];
    const float* v_a    = (const float*)d_in[10];
    const float* v_b    = (const float*)d_in[11];
    const float* v_l    = (const float*)d_in[12];
    const float* proj_w = (const float*)d_in[13];
    const float* proj_b = (const float*)d_in[14];
    float* out = (float*)d_out;

    float *p_q, *p_k, *p_v;
    cudaGetSymbolAddress((void**)&p_q, g_q);
    cudaGetSymbolAddress((void**)&p_k, g_k);
    cudaGetSymbolAddress((void**)&p_v, g_v);

    cudaFuncSetAttribute(gemm_qkv_kernel,
                         cudaFuncAttributeMaxDynamicSharedMemorySize, GSMEM);
    cudaFuncSetAttribute(gemm_proj_kernel,
                         cudaFuncAttributeMaxDynamicSharedMemorySize, GSMEM);
    cudaFuncSetAttribute(attn_mma_kernel,
                         cudaFuncAttributeMaxDynamicSharedMemorySize, ATTN_SMEM);

    split_w4_kernel<<<dim3((DIMN*DIMN)/256, 4), 256>>>(q_w, k_w, v_w, proj_w);
    lora_h_kernel<<<MTOK/8, 256>>>(x, q_a, k_a, v_a);
    mod_input_kernel<<<dim3(MTOK/32, 3), 256>>>(x, q_b, q_l, k_b, k_l, v_b, v_l);

    gemm_qkv_kernel<<<dim3(8, 16, 3), 256, GSMEM>>>();

    rope_split_kernel<<<(3*MTOK*NHEADS*32)/256, 256>>>(p_q, p_k, p_v);
    attn_mma_kernel<<<1024, 128, ATTN_SMEM>>>();

    gemm_proj_kernel<<<dim3(8, 16), 256, GSMEM>>>(proj_b, out);
}

// round 11
// speedup vs baseline: 4.7719x; 1.0061x over previous
#include <cuda_runtime.h>
#include <cuda_bf16.h>
#include <cuda_fp16.h>
#include <cstdint>
#include <stdint.h>
#include <math.h>

#define DIMN   1024
#define NHEADS 16
#define HDIM   64
#define LORA_D 16
#define BB     4
#define TT     1024
#define MTOK   (BB*TT)   // 4096
#define KCATP  2048      // proj: 2-term fp16 split

// ---------------- scratch ----------------
__device__ float g_h[MTOK*48];
__device__ __half g_qcat[(size_t)MTOK*DIMN];   // qkv acts: single fp16 term
__device__ __half g_kcat[(size_t)MTOK*DIMN];
__device__ __half g_vcat[(size_t)MTOK*DIMN];
__device__ __half g_acat[(size_t)MTOK*KCATP];  // proj input [hi|lo], written by attention
__device__ __half g_wq[(size_t)DIMN*DIMN];
__device__ __half g_wk[(size_t)DIMN*DIMN];
__device__ __half g_wv[(size_t)DIMN*DIMN];
__device__ __half g_wp[(size_t)DIMN*DIMN];
__device__ __half g_qh[(size_t)MTOK*DIMN];     // [bh][t][64]
__device__ __half g_kh[(size_t)MTOK*DIMN];
__device__ __half g_vh[(size_t)MTOK*DIMN];
__device__ float2 g_rope[TT*32];               // (cos, sin) per (t, j)

// ---------------- asm helpers ----------------
__device__ __forceinline__ void cpa16(unsigned int d, const void* s) {
    asm volatile("cp.async.cg.shared.global [%0], [%1], 16;\n" :: "r"(d), "l"(s));
}
__device__ __forceinline__ void ldsm4(unsigned int a, unsigned int* r) {
    asm volatile("ldmatrix.sync.aligned.m8n8.x4.shared.b16 {%0,%1,%2,%3}, [%4];\n"
        : "=r"(r[0]), "=r"(r[1]), "=r"(r[2]), "=r"(r[3]) : "r"(a));
}
__device__ __forceinline__ void ldsm4t(unsigned int a, unsigned int* r) {
    asm volatile("ldmatrix.sync.aligned.m8n8.x4.trans.shared.b16 {%0,%1,%2,%3}, [%4];\n"
        : "=r"(r[0]), "=r"(r[1]), "=r"(r[2]), "=r"(r[3]) : "r"(a));
}
__device__ __forceinline__ void mmah(float* c, unsigned int a0, unsigned int a1,
                                     unsigned int a2, unsigned int a3,
                                     unsigned int b0, unsigned int b1) {
    asm volatile("mma.sync.aligned.m16n8k16.row.col.f32.f16.f16.f32 "
        "{%0,%1,%2,%3},{%4,%5,%6,%7},{%8,%9},{%0,%1,%2,%3};\n"
        : "+f"(c[0]), "+f"(c[1]), "+f"(c[2]), "+f"(c[3])
        : "r"(a0), "r"(a1), "r"(a2), "r"(a3), "r"(b0), "r"(b1));
}
__device__ __forceinline__ unsigned int ex2h2(unsigned int x) {
    unsigned int d;
    asm("ex2.approx.f16x2 %0, %1;" : "=r"(d) : "r"(x));
    return d;
}
__device__ __forceinline__ unsigned int cvt2h(float hi, float lo) {
    unsigned int d;
    asm("cvt.rn.f16x2.f32 %0, %1, %2;" : "=r"(d) : "f"(hi), "f"(lo));
    return d;
}

// ---------------- kernel 0: rope table ----------------
__global__ void __launch_bounds__(256) rope_tab_kernel() {
    const int idx = blockIdx.x * 256 + threadIdx.x;     // 32768
    const int t = idx >> 5, j = idx & 31;
    float theta = 1.0f / powf(10000.0f, (float)j * (1.0f / 32.0f));
    float ang = (float)t * theta;
    float sn, cs;
    sincosf(ang, &sn, &cs);
    g_rope[idx] = make_float2(cs, sn);
}

// ---------------- kernel 1: H = tanh(x @ Acat^T) ----------
__global__ void __launch_bounds__(256) lora_h_kernel(const float* __restrict__ x,
                                                     const float* __restrict__ qa,
                                                     const float* __restrict__ ka,
                                                     const float* __restrict__ va) {
    __shared__ float xs[8][DIMN];
    const int tok0 = blockIdx.x * 8;
    const int tid  = threadIdx.x;

    const float4* xg  = (const float4*)(x + (size_t)tok0 * DIMN);
    float4*       xs4 = (float4*)&xs[0][0];
#pragma unroll
    for (int i = 0; i < 8; i++) xs4[tid + i*256] = xg[tid + i*256];
    __syncthreads();

    const int warp = tid >> 5, lane = tid & 31;
#pragma unroll
    for (int jj = 0; jj < 6; jj++) {
        const int j = warp * 6 + jj;
        const float* a = (j < 16) ? (qa + j*DIMN)
                       : (j < 32) ? (ka + (j-16)*DIMN)
                                  : (va + (j-32)*DIMN);
        float acc[8];
#pragma unroll
        for (int t = 0; t < 8; t++) acc[t] = 0.f;
        for (int i = 0; i < 32; i++) {
            float av = a[lane + i*32];
#pragma unroll
            for (int t = 0; t < 8; t++) acc[t] += xs[t][lane + i*32] * av;
        }
#pragma unroll
        for (int off = 16; off; off >>= 1) {
#pragma unroll
            for (int t = 0; t < 8; t++)
                acc[t] += __shfl_xor_sync(0xffffffffu, acc[t], off);
        }
        if (lane == 0) {
#pragma unroll
            for (int t = 0; t < 8; t++)
                g_h[(size_t)(tok0 + t)*48 + j] = tanhf(acc[t]);
        }
    }
}

// ---------------- kernel 2: mod inputs -> fp16 (all 3 in one pass over x) ------
__global__ void __launch_bounds__(256) mod_input3_kernel(const float* __restrict__ x,
                                                         const float* __restrict__ qb, const float* __restrict__ ql,
                                                         const float* __restrict__ kb, const float* __restrict__ kl,
                                                         const float* __restrict__ vb, const float* __restrict__ vl) {
    const int tok0 = blockIdx.x * 32;
    __shared__ float hs[32][48];
    const int tid = threadIdx.x;
    for (int i = tid; i < 32*48; i += 256) {
        int t = i / 48, j = i % 48;
        hs[t][j] = g_h[(size_t)(tok0 + t)*48 + j];
    }
    __syncthreads();

#pragma unroll
    for (int c = 0; c < 4; c++) {
        const int d = tid + c*256;
        float bq[LORA_D], bk[LORA_D], bv[LORA_D];
        const float4* qrow = (const float4*)(qb + (size_t)d * LORA_D);
        const float4* krow = (const float4*)(kb + (size_t)d * LORA_D);
        const float4* vrow = (const float4*)(vb + (size_t)d * LORA_D);
#pragma unroll
        for (int q4 = 0; q4 < 4; q4++) {
            float4 w;
            w = qrow[q4]; bq[q4*4+0]=w.x; bq[q4*4+1]=w.y; bq[q4*4+2]=w.z; bq[q4*4+3]=w.w;
            w = krow[q4]; bk[q4*4+0]=w.x; bk[q4*4+1]=w.y; bk[q4*4+2]=w.z; bk[q4*4+3]=w.w;
            w = vrow[q4]; bv[q4*4+0]=w.x; bv[q4*4+1]=w.y; bv[q4*4+2]=w.z; bv[q4*4+3]=w.w;
        }
        const float lq = ql[d], lk = kl[d], lv = vl[d];
        float xprev = ((tok0 % TT) == 0) ? 0.f : x[(size_t)(tok0 - 1)*DIMN + d];
        for (int t = 0; t < 32; t++) {
            float xv = x[(size_t)(tok0 + t)*DIMN + d];
            float rq = lq, rk = lk, rv = lv;
#pragma unroll
            for (int j = 0; j < LORA_D; j++) {
                rq += hs[t][j]      * bq[j];
                rk += hs[t][16 + j] * bk[j];
                rv += hs[t][32 + j] * bv[j];
            }
            const float dx = xprev - xv;
            const size_t o = (size_t)(tok0 + t)*DIMN + d;
            g_qcat[o] = __float2half_rn(xv + dx*rq);
            g_kcat[o] = __float2half_rn(xv + dx*rk);
            g_vcat[o] = __float2half_rn(xv + dx*rv);
            xprev = xv;
        }
    }
}

// ---------------- kernel 2c: all 4 weights -> fp16 ----------------
__global__ void __launch_bounds__(256) split_w4_kernel(const float* __restrict__ qw,
                                                       const float* __restrict__ kw,
                                                       const float* __restrict__ vw,
                                                       const float* __restrict__ pw) {
    const int which = blockIdx.y;
    const float* in = (which == 0) ? qw : (which == 1) ? kw : (which == 2) ? vw : pw;
    __half* out = (which == 0) ? g_wq : (which == 1) ? g_wk : (which == 2) ? g_wv : g_wp;
    const int idx = blockIdx.x * 256 + threadIdx.x;
    out[idx] = __float2half_rn(in[idx]);
}

// ---------------- GEMM body: 256x128 tile, 3-stage ----------------
// MODE 0: fp32 C store (+bias).  MODE 1: fused RoPE/cvt fp16 store to OH in [bh][t][64]
#define GSTAGE 49152
#define GSMEM  (3*GSTAGE)

template<int KACT, int NIT, int MODE>
__device__ __forceinline__ void gemm_body(const __half* __restrict__ A,
                                          const __half* __restrict__ W,
                                          const float* __restrict__ bias,
                                          float* __restrict__ C,
                                          __half* __restrict__ OH,
                                          int do_rope,
                                          char* smem, int bx, int by) {
    const unsigned int su = (unsigned int)__cvta_generic_to_shared(smem);
    const int tid  = threadIdx.x;
    const int lane = tid & 31, warp = tid >> 5;
    const int wm = warp >> 1, wn = warp & 1;
    const int m0 = by * 256, n0 = bx * 128;

    float acc[4][8][4];
#pragma unroll
    for (int i = 0; i < 4; i++)
#pragma unroll
        for (int j = 0; j < 8; j++)
#pragma unroll
            for (int e = 0; e < 4; e++) acc[i][j][e] = 0.f;

    const int crow = tid >> 3;
    const int cc   = tid & 7;

    auto issue = [&](int s) {
        const int k0 = s * 64;
        const int kw = k0 & 1023;
        const unsigned int base = su + (unsigned int)((s % 3) * GSTAGE);
#pragma unroll
        for (int e = 0; e < 8; e++) {
            const int row = crow + e * 32;
            const unsigned int sw = (unsigned int)((cc ^ (row & 7)) << 4);
            cpa16(base + row*128 + sw, A + (size_t)(m0 + row)*KACT + k0 + cc*8);
        }
#pragma unroll
        for (int e = 0; e < 4; e++) {
            const int row = crow + e * 32;
            const unsigned int sw = (unsigned int)((cc ^ (row & 7)) << 4);
            cpa16(base + 32768 + row*128 + sw, W + (size_t)(n0 + row)*DIMN + kw + cc*8);
        }
        asm volatile("cp.async.commit_group;\n");
    };

    issue(0);
    issue(1);

    const int krow = lane & 15;
    const int hi16 = lane >> 4;

    for (int it = 0; it < NIT; it++) {
        if (it < NIT-1) asm volatile("cp.async.wait_group 1;\n");
        else            asm volatile("cp.async.wait_group 0;\n");
        __syncthreads();
        if (it + 2 < NIT) issue(it + 2);

        const unsigned int Ab = su + (unsigned int)((it % 3) * GSTAGE);
        const unsigned int Wb = Ab + 32768;

#pragma unroll
        for (int ks = 0; ks < 4; ks++) {
            unsigned int a[4][4], b[4][4];
#pragma unroll
            for (int im = 0; im < 4; im++) {
                const int row = wm*64 + im*16 + krow;
                ldsm4(Ab + (unsigned int)(row*128 + (((2*ks + hi16) ^ (row & 7)) << 4)), a[im]);
            }
#pragma unroll
            for (int jn = 0; jn < 4; jn++) {
                const int row = wn*64 + jn*16 + krow;
                ldsm4(Wb + (unsigned int)(row*128 + (((2*ks + hi16) ^ (row & 7)) << 4)), b[jn]);
            }
#pragma unroll
            for (int im = 0; im < 4; im++)
#pragma unroll
                for (int j8 = 0; j8 < 8; j8++) {
                    const int jn = j8 >> 1, p = j8 & 1;
                    mmah(acc[im][j8], a[im][0], a[im][1], a[im][2], a[im][3],
                         b[jn][p], b[jn][2 + p]);
                }
        }
    }

    if (MODE == 0) {
#pragma unroll
        for (int im = 0; im < 4; im++) {
            const int r0 = m0 + wm*64 + im*16 + (lane >> 2);
#pragma unroll
            for (int j8 = 0; j8 < 8; j8++) {
                const int col = n0 + wn*64 + j8*8 + 2*(lane & 3);
                float b0 = 0.f, b1 = 0.f;
                if (bias) { b0 = bias[col]; b1 = bias[col + 1]; }
                *(float2*)&C[(size_t)r0*1024 + col]       = make_float2(acc[im][j8][0] + b0, acc[im][j8][1] + b1);
                *(float2*)&C[(size_t)(r0 + 8)*1024 + col] = make_float2(acc[im][j8][2] + b0, acc[im][j8][3] + b1);
            }
        }
    } else {
        const int head = bx*2 + wn;                     // 2 heads per N-tile
#pragma unroll
        for (int im = 0; im < 4; im++) {
            const int r0 = m0 + wm*64 + im*16 + (lane >> 2);
            const int b = r0 >> 10, t0 = r0 & 1023, t1 = t0 + 8;
            const size_t d0 = ((size_t)(b*16 + head)*TT + t0)*HDIM;
            const size_t d1 = d0 + 8*HDIM;
            if (do_rope) {
#pragma unroll
                for (int j8 = 0; j8 < 4; j8++) {
                    const int hd = j8*8 + 2*(lane & 3);
                    const float2 ca0 = g_rope[t0*32 + hd];
                    const float2 cb0 = g_rope[t0*32 + hd + 1];
                    const float2 ca1 = g_rope[t1*32 + hd];
                    const float2 cb1 = g_rope[t1*32 + hd + 1];
                    const float xr0 = acc[im][j8][0],   xi0 = acc[im][j8+4][0];
                    const float xr1 = acc[im][j8][1],   xi1 = acc[im][j8+4][1];
                    const float xr2 = acc[im][j8][2],   xi2 = acc[im][j8+4][2];
                    const float xr3 = acc[im][j8][3],   xi3 = acc[im][j8+4][3];
                    *(__half2*)&OH[d0 + hd] = __halves2half2(
                        __float2half_rn(xr0*ca0.x - xi0*ca0.y),
                        __float2half_rn(xr1*cb0.x - xi1*cb0.y));
                    *(__half2*)&OH[d0 + hd + 32] = __halves2half2(
                        __float2half_rn(xr0*ca0.y + xi0*ca0.x),
                        __float2half_rn(xr1*cb0.y + xi1*cb0.x));
                    *(__half2*)&OH[d1 + hd] = __halves2half2(
                        __float2half_rn(xr2*ca1.x - xi2*ca1.y),
                        __float2half_rn(xr3*cb1.x - xi3*cb1.y));
                    *(__half2*)&OH[d1 + hd + 32] = __halves2half2(
                        __float2half_rn(xr2*ca1.y + xi2*ca1.x),
                        __float2half_rn(xr3*cb1.y + xi3*cb1.x));
                }
            } else {
#pragma unroll
                for (int j8 = 0; j8 < 8; j8++) {
                    const int hd = j8*8 + 2*(lane & 3);
                    *(__half2*)&OH[d0 + hd] = __halves2half2(
                        __float2half_rn(acc[im][j8][0]), __float2half_rn(acc[im][j8][1]));
                    *(__half2*)&OH[d1 + hd] = __halves2half2(
                        __float2half_rn(acc[im][j8][2]), __float2half_rn(acc[im][j8][3]));
                }
            }
        }
    }
}

// batched q/k/v GEMM (single-term, K=1024) with fused RoPE/cvt epilogue
__global__ void __launch_bounds__(256, 1) gemm_qkv_kernel() {
    extern __shared__ char smem[];
    const int z = blockIdx.z;
    const __half* A = (z == 0) ? g_qcat : (z == 1) ? g_kcat : g_vcat;
    const __half* W = (z == 0) ? g_wq   : (z == 1) ? g_wk   : g_wv;
    __half*      O = (z == 0) ? g_qh   : (z == 1) ? g_kh   : g_vh;
    gemm_body<DIMN, 16, 1>(A, W, nullptr, nullptr, O, (z < 2) ? 1 : 0,
                           smem, blockIdx.x, blockIdx.y);
}

// proj GEMM (2-term, K=2048)
__global__ void __launch_bounds__(256, 1) gemm_proj_kernel(const float* __restrict__ bias,
                                                           float* __restrict__ out) {
    extern __shared__ char smem[];
    gemm_body<KCATP, 32, 0>(g_acat, g_wp, bias, out, nullptr, 0,
                            smem, blockIdx.x, blockIdx.y);
}

// ---------------- kernel 5: tensor-core causal flash attention (1-seg QK, 1-term PV) --------
#define ATTN_SMEM 40960

__global__ void __launch_bounds__(128, 3) attn_mma_kernel() {
    extern __shared__ char smx[];
    const unsigned int su = (unsigned int)__cvta_generic_to_shared(smx);
    const int tid = threadIdx.x, lane = tid & 31, warp = tid >> 5;
    const int bx = blockIdx.x;
    const int qt = 15 - (bx >> 6);
    const int bh = bx & 63;
    const int q0 = qt * 64;
    const int nk = qt + 1;
    const size_t hb = (size_t)bh * (TT * HDIM);

    auto ldt = [&](unsigned int dstBase, const __half* g, int row0) {
#pragma unroll
        for (int e2 = 0; e2 < 4; e2++) {
            int idx = tid + e2*128;
            int r = idx >> 3, ch = idx & 7;
            cpa16(dstBase + (unsigned int)(r*128 + ((ch ^ (r & 7)) << 4)),
                  g + hb + (size_t)(row0 + r)*HDIM + ch*8);
        }
    };
    auto issue_kv = [&](int kt) {
        unsigned int base = su + 8192u + (unsigned int)((kt & 1) * 16384);
        ldt(base,         g_kh, kt*64);
        ldt(base + 8192u, g_vh, kt*64);
        asm volatile("cp.async.commit_group;\n");
    };

    ldt(su, g_qh, q0);
    asm volatile("cp.async.commit_group;\n");
    issue_kv(0);
    if (nk > 1) { issue_kv(1); asm volatile("cp.async.wait_group 1;\n"); }
    else        {              asm volatile("cp.async.wait_group 0;\n"); }
    __syncthreads();

    const int hi16 = lane >> 4;
    const int krow = lane & 15;
    const int wrow = warp*16 + (lane >> 2);

    unsigned int aq[4][4];
    {
        const int qrow = warp*16 + krow;
#pragma unroll
        for (int ck = 0; ck < 4; ck++)
            ldsm4(su + (unsigned int)(qrow*128 + (((2*ck + hi16) ^ (qrow & 7)) << 4)), aq[ck]);
    }

    float oacc[8][4], lacc[4];
#pragma unroll
    for (int j = 0; j < 8; j++)
#pragma unroll
        for (int e = 0; e < 4; e++) oacc[j][e] = 0.f;
#pragma unroll
    for (int e = 0; e < 4; e++) lacc[e] = 0.f;
    float m0 = -1e30f, m1 = -1e30f;

    const unsigned int ONES = 0x3C003C00u;

    for (int kt = 0; kt < nk; kt++) {
        const unsigned int sb = su + 8192u + (unsigned int)((kt & 1) * 16384);

        float c[8][4];
#pragma unroll
        for (int j = 0; j < 8; j++)
#pragma unroll
            for (int e = 0; e < 4; e++) c[j][e] = 0.f;

        // ---- S = Qh · Kh^T ----
#pragma unroll
        for (int ck = 0; ck < 4; ck++) {
#pragma unroll
            for (int g = 0; g < 4; g++) {
                unsigned int bq[4];
                const int row = g*16 + krow;
                ldsm4(sb + (unsigned int)(row*128 + (((2*ck + hi16) ^ (row & 7)) << 4)), bq);
                mmah(c[2*g],   aq[ck][0], aq[ck][1], aq[ck][2], aq[ck][3], bq[0], bq[2]);
                mmah(c[2*g+1], aq[ck][0], aq[ck][1], aq[ck][2], aq[ck][3], bq[1], bq[3]);
            }
        }

        const float alpha = 0.18033688011112042f;   // 0.125 * log2(e)
#pragma unroll
        for (int j = 0; j < 8; j++) {
            c[j][0] *= alpha; c[j][1] *= alpha; c[j][2] *= alpha; c[j][3] *= alpha;
        }
        if (kt == qt) {
#pragma unroll
            for (int j = 0; j < 8; j++) {
                const int cb = 8*j + 2*(lane & 3);
                if (cb     > wrow)     c[j][0] = -30000.f;
                if (cb + 1 > wrow)     c[j][1] = -30000.f;
                if (cb     > wrow + 8) c[j][2] = -30000.f;
                if (cb + 1 > wrow + 8) c[j][3] = -30000.f;
            }
        }
        float ml0 = -1e30f, ml1 = -1e30f;
#pragma unroll
        for (int j = 0; j < 8; j++) {
            ml0 = fmaxf(ml0, fmaxf(c[j][0], c[j][1]));
            ml1 = fmaxf(ml1, fmaxf(c[j][2], c[j][3]));
        }
#pragma unroll
        for (int off = 1; off <= 2; off <<= 1) {
            ml0 = fmaxf(ml0, __shfl_xor_sync(0xffffffffu, ml0, off));
            ml1 = fmaxf(ml1, __shfl_xor_sync(0xffffffffu, ml1, off));
        }
        const float mn0 = fmaxf(m0, ml0), mn1 = fmaxf(m1, ml1);
        const float cr0 = exp2f(m0 - mn0), cr1 = exp2f(m1 - mn1);
        m0 = mn0; m1 = mn1;

        unsigned int pf[2][8];
#pragma unroll
        for (int j = 0; j < 8; j++) {
            pf[0][j] = ex2h2(cvt2h(c[j][1] - m0, c[j][0] - m0));
            pf[1][j] = ex2h2(cvt2h(c[j][3] - m1, c[j][2] - m1));
        }
#pragma unroll
        for (int j = 0; j < 8; j++) {
            oacc[j][0] *= cr0; oacc[j][1] *= cr0;
            oacc[j][2] *= cr1; oacc[j][3] *= cr1;
        }
        lacc[0] *= cr0; lacc[1] *= cr0; lacc[2] *= cr1; lacc[3] *= cr1;

        // ---- O += P Vh, l += P @ ones ----
        const unsigned int Vb = sb + 8192u;
#pragma unroll
        for (int kc = 0; kc < 4; kc++) {
            const unsigned int a0 = pf[0][2*kc],   a1 = pf[1][2*kc];
            const unsigned int a2 = pf[0][2*kc+1], a3 = pf[1][2*kc+1];
            mmah(lacc, a0, a1, a2, a3, ONES, ONES);
            const int rbase = kc*16 + krow;
#pragma unroll
            for (int jj = 0; jj < 4; jj++) {
                unsigned int bv[4];
                ldsm4t(Vb + (unsigned int)(rbase*128 + (((2*jj + hi16) ^ (rbase & 7)) << 4)), bv);
                mmah(oacc[2*jj],   a0, a1, a2, a3, bv[0], bv[1]);
                mmah(oacc[2*jj+1], a0, a1, a2, a3, bv[2], bv[3]);
            }
        }

        if (kt + 1 < nk) {
            __syncthreads();
            if (kt + 2 < nk) {
                issue_kv(kt + 2);
                asm volatile("cp.async.wait_group 1;\n");
            } else {
                asm volatile("cp.async.wait_group 0;\n");
            }
            __syncthreads();
        }
    }

    // ---- epilogue: write fp16 [hi|lo] into g_acat ([tok][2048]) ----
    const float inv0 = 1.f / lacc[0];
    const float inv1 = 1.f / lacc[2];
    const int b = bh >> 4, h = bh & 15;
    const size_t tok0 = (size_t)b*TT + q0 + wrow;
#pragma unroll
    for (int j = 0; j < 8; j++) {
        const int col = 8*j + 2*(lane & 3);
        float a0 = oacc[j][0]*inv0, a1 = oacc[j][1]*inv0;
        float a2 = oacc[j][2]*inv1, a3 = oacc[j][3]*inv1;
        __half h0 = __float2half_rn(a0), h1 = __float2half_rn(a1);
        __half h2 = __float2half_rn(a2), h3 = __float2half_rn(a3);
        __half l0 = __float2half_rn(a0 - __half2float(h0));
        __half l1 = __float2half_rn(a1 - __half2float(h1));
        __half l2 = __float2half_rn(a2 - __half2float(h2));
        __half l3 = __float2half_rn(a3 - __half2float(h3));
        size_t base0 = tok0*KCATP + h*HDIM + col;
        size_t base1 = (tok0 + 8)*KCATP + h*HDIM + col;
        *(__half2*)&g_acat[base0]        = __halves2half2(h0, h1);
        *(__half2*)&g_acat[base0 + 1024] = __halves2half2(l0, l1);
        *(__half2*)&g_acat[base1]        = __halves2half2(h2, h3);
        *(__half2*)&g_acat[base1 + 1024] = __halves2half2(l2, l3);
    }
}

// ---------------- launch ----------------
extern "C" void kernel_launch(void* const* d_in, const int* in_sizes, int n_in,
                              void* d_out, int out_size) {
    const float* x      = (const float*)d_in[0];
    const float* q_w    = (const float*)d_in[1];
    const float* k_w    = (const float*)d_in[2];
    const float* v_w    = (const float*)d_in[3];
    const float* q_a    = (const float*)d_in[4];
    const float* q_b    = (const float*)d_in[5];
    const float* q_l    = (const float*)d_in[6];
    const float* k_a    = (const float*)d_in[7];
    const float* k_b    = (const float*)d_in[8];
    const float* k_l    = (const float*)d_in[9];
    const float* v_a    = (const float*)d_in[10];
    const float* v_b    = (const float*)d_in[11];
    const float* v_l    = (const float*)d_in[12];
    const float* proj_w = (const float*)d_in[13];
    const float* proj_b = (const float*)d_in[14];
    float* out = (float*)d_out;

    cudaFuncSetAttribute(gemm_qkv_kernel,
                         cudaFuncAttributeMaxDynamicSharedMemorySize, GSMEM);
    cudaFuncSetAttribute(gemm_proj_kernel,
                         cudaFuncAttributeMaxDynamicSharedMemorySize, GSMEM);
    cudaFuncSetAttribute(attn_mma_kernel,
                         cudaFuncAttributeMaxDynamicSharedMemorySize, ATTN_SMEM);

    rope_tab_kernel<<<(TT*32)/256, 256>>>();
    split_w4_kernel<<<dim3((DIMN*DIMN)/256, 4), 256>>>(q_w, k_w, v_w, proj_w);
    lora_h_kernel<<<MTOK/8, 256>>>(x, q_a, k_a, v_a);
    mod_input3_kernel<<<MTOK/32, 256>>>(x, q_b, q_l, k_b, k_l, v_b, v_l);

    gemm_qkv_kernel<<<dim3(8, 16, 3), 256, GSMEM>>>();

    attn_mma_kernel<<<1024, 128, ATTN_SMEM>>>();

    gemm_proj_kernel<<<dim3(8, 16), 256, GSMEM>>>(proj_b, out);
}